// round 2
// baseline (speedup 1.0000x reference)
#include <cuda_runtime.h>
#include <math.h>

#define B_    16
#define INC   1024
#define P_    256
#define HEADS 4
#define D_    64
#define N_    1024     // W*H = 32*32
#define WW    32
#define HH    32

// ---------------- scratch (static device globals; no allocations) ----------
__device__ float g_buf[B_*P_*N_];                 // downsample out   [b][p][n]
__device__ float g_q  [B_*P_*N_];                 // q                [b][p][n]
__device__ float g_k  [B_*P_*N_];
__device__ float g_v  [B_*P_*N_];
__device__ float g_Qp [B_*HEADS*128*N_];          // Q' = [q;pos]     [bh][dd][n]
__device__ float g_Kp [B_*HEADS*128*N_];          // K' = [k;q]       [bh][dd][n]
__device__ float g_Vt [B_*HEADS*N_*D_];           // V transposed     [bh][n][d]
__device__ float g_S  [67108864];                 // logits/attn      [bh][i][j]  (256MB)
__device__ float g_Ot [B_*HEADS*N_*D_];           // attn out         [bh][i][d]
__device__ float g_Y  [B_*P_*N_];                 // post-LN          [b][p][n]

// ---------------- generic tiled SGEMM ---------------------------------------
// C[M][Ncols] = A * B  (per-batch via grid.z; strides sA/sB/sC/sR, 0 = shared)
// TRANS_A=0: A is [M][K] row-major.  TRANS_A=1: A is [K][M] row-major (TN form).
// B is [K][Ncols] row-major.  EPI=1: C = gelu(acc+bias) + resid.
template<int TRANS_A, int EPI>
__global__ __launch_bounds__(256)
void gemm_kernel(const float* __restrict__ A, const float* __restrict__ Bm,
                 float* __restrict__ C, const float* __restrict__ bias,
                 const float* __restrict__ resid,
                 int M, int Ncols, int K,
                 long long sA, long long sB, long long sC, long long sR)
{
    const int BM = 128, BN = 128, BK = 16;
    __shared__ float As[BK][BM + 4];
    __shared__ float Bs[BK][BN];

    const int bz = blockIdx.z;
    A  += sA * bz;
    Bm += sB * bz;
    C  += sC * bz;
    const float* R = (EPI == 1) ? (resid + sR * bz) : nullptr;

    const int m0 = blockIdx.y * BM;
    const int n0 = blockIdx.x * BN;
    const int tid = threadIdx.x;
    const int tx = tid & 15;        // 0..15  -> n
    const int ty = tid >> 4;        // 0..15  -> m

    float acc[8][8];
    #pragma unroll
    for (int i = 0; i < 8; i++)
        #pragma unroll
        for (int j = 0; j < 8; j++) acc[i][j] = 0.0f;

    for (int k0 = 0; k0 < K; k0 += BK) {
        // ---- load A tile ----
        if (TRANS_A) {
            // A[k][m] : 16 rows x 128 cols -> same pattern as B
            int r  = tid >> 5;            // 0..7
            int c4 = tid & 31;            // 0..31
            #pragma unroll
            for (int p = 0; p < 2; p++) {
                int k = r + p * 8;
                float4 v4 = *reinterpret_cast<const float4*>(
                    &A[(long long)(k0 + k) * M + m0 + c4 * 4]);
                *reinterpret_cast<float4*>(&As[k][c4 * 4]) = v4;
            }
        } else {
            // A[m][k] : 128 rows x 16 cols, transpose into As
            int r  = tid >> 2;            // 0..63
            int c4 = tid & 3;             // 0..3
            #pragma unroll
            for (int p = 0; p < 2; p++) {
                int m = r + p * 64;
                float4 v4 = *reinterpret_cast<const float4*>(
                    &A[(long long)(m0 + m) * K + k0 + c4 * 4]);
                As[c4 * 4 + 0][m] = v4.x;
                As[c4 * 4 + 1][m] = v4.y;
                As[c4 * 4 + 2][m] = v4.z;
                As[c4 * 4 + 3][m] = v4.w;
            }
        }
        // ---- load B tile ----
        {
            int r  = tid >> 5;
            int c4 = tid & 31;
            #pragma unroll
            for (int p = 0; p < 2; p++) {
                int k = r + p * 8;
                int n = n0 + c4 * 4;
                float4 v4 = make_float4(0.f, 0.f, 0.f, 0.f);
                if (n < Ncols)
                    v4 = *reinterpret_cast<const float4*>(
                        &Bm[(long long)(k0 + k) * Ncols + n]);
                *reinterpret_cast<float4*>(&Bs[k][c4 * 4]) = v4;
            }
        }
        __syncthreads();

        #pragma unroll
        for (int kk = 0; kk < BK; kk++) {
            float af[8], bf[8];
            *reinterpret_cast<float4*>(&af[0]) = *reinterpret_cast<float4*>(&As[kk][ty * 8]);
            *reinterpret_cast<float4*>(&af[4]) = *reinterpret_cast<float4*>(&As[kk][ty * 8 + 4]);
            *reinterpret_cast<float4*>(&bf[0]) = *reinterpret_cast<float4*>(&Bs[kk][tx * 8]);
            *reinterpret_cast<float4*>(&bf[4]) = *reinterpret_cast<float4*>(&Bs[kk][tx * 8 + 4]);
            #pragma unroll
            for (int i = 0; i < 8; i++)
                #pragma unroll
                for (int j = 0; j < 8; j++)
                    acc[i][j] = fmaf(af[i], bf[j], acc[i][j]);
        }
        __syncthreads();
    }

    // ---- epilogue ----
    #pragma unroll
    for (int i = 0; i < 8; i++) {
        int m = m0 + ty * 8 + i;
        float bv = bias ? bias[m] : 0.0f;
        #pragma unroll
        for (int j = 0; j < 8; j++) {
            int n = n0 + tx * 8 + j;
            if (n < Ncols) {
                float val = acc[i][j] + bv;
                long long off = (long long)m * Ncols + n;
                if (EPI == 1) {
                    val = 0.5f * val * (1.0f + erff(val * 0.70710678118654752f));
                    val += R[off];
                }
                C[off] = val;
            }
        }
    }
}

// ---------------- build Q' and K' -------------------------------------------
__global__ void prep_qk(const float* __restrict__ q, const float* __restrict__ k,
                        const float* __restrict__ rel_h, const float* __restrict__ rel_w,
                        float* __restrict__ Qp, float* __restrict__ Kp)
{
    long long idx = (long long)blockIdx.x * blockDim.x + threadIdx.x;
    if (idx >= (long long)B_ * HEADS * 128 * N_) return;
    int n  = idx & (N_ - 1);
    int dd = (idx >> 10) & 127;
    int bh = (int)(idx >> 17);
    int b = bh >> 2, h = bh & 3;

    float qv, kv;
    if (dd < D_) {
        long long src = ((long long)(b * P_ + h * D_ + dd)) * N_ + n;
        qv = q[src];
        kv = k[src];
    } else {
        int d = dd - D_;
        int w = n >> 5, hh = n & 31;
        qv = rel_h[(h * D_ + d) * HH + hh] + rel_w[(h * D_ + d) * WW + w];
        kv = q[((long long)(b * P_ + h * D_ + d)) * N_ + n];
    }
    Qp[idx] = qv;
    Kp[idx] = kv;
}

// ---------------- transpose V: [d][n] -> [n][d] per (b,h) -------------------
__global__ void transpose_v(const float* __restrict__ v, float* __restrict__ Vt)
{
    __shared__ float t[32][33];
    int bh = blockIdx.z;
    int b = bh >> 2, h = bh & 3;
    int n0 = blockIdx.x * 32;
    int d0 = blockIdx.y * 32;
    int x = threadIdx.x, y = threadIdx.y;

    t[y][x] = v[((long long)(b * P_ + h * D_ + d0 + y)) * N_ + n0 + x];
    __syncthreads();
    Vt[((long long)bh * N_ + n0 + y) * D_ + d0 + x] = t[x][y];
}

// ---------------- row softmax (warp per 1024-row) ----------------------------
__global__ void softmax_kernel(float* __restrict__ S)
{
    int gw = (blockIdx.x * blockDim.x + threadIdx.x) >> 5;
    int lane = threadIdx.x & 31;
    if (gw >= B_ * HEADS * N_) return;
    float4* row = reinterpret_cast<float4*>(S + (long long)gw * N_);

    float4 v[8];
    float mx = -1e30f;
    #pragma unroll
    for (int i = 0; i < 8; i++) {
        v[i] = row[lane + 32 * i];
        mx = fmaxf(mx, fmaxf(fmaxf(v[i].x, v[i].y), fmaxf(v[i].z, v[i].w)));
    }
    #pragma unroll
    for (int o = 16; o; o >>= 1) mx = fmaxf(mx, __shfl_xor_sync(0xffffffffu, mx, o));

    float sum = 0.0f;
    #pragma unroll
    for (int i = 0; i < 8; i++) {
        v[i].x = expf(v[i].x - mx);
        v[i].y = expf(v[i].y - mx);
        v[i].z = expf(v[i].z - mx);
        v[i].w = expf(v[i].w - mx);
        sum += v[i].x + v[i].y + v[i].z + v[i].w;
    }
    #pragma unroll
    for (int o = 16; o; o >>= 1) sum += __shfl_xor_sync(0xffffffffu, sum, o);
    float inv = 1.0f / sum;

    #pragma unroll
    for (int i = 0; i < 8; i++) {
        v[i].x *= inv; v[i].y *= inv; v[i].z *= inv; v[i].w *= inv;
        row[lane + 32 * i] = v[i];
    }
}

// ---------------- LayerNorm over channels + transpose back to [b][p][n] -----
__global__ void ln_kernel(const float* __restrict__ Ot,
                          const float* __restrict__ ln_w, const float* __restrict__ ln_b,
                          float* __restrict__ Y)
{
    __shared__ float s[32][257];
    __shared__ float smu[32], srs[32];
    int b  = blockIdx.y;
    int n0 = blockIdx.x * 32;
    int tid = threadIdx.x;

    // load 32 spatial positions x 256 channels, coalesced along d
    for (int idx = tid; idx < 32 * 256; idx += 256) {
        int p  = idx & 255;
        int ni = idx >> 8;
        int h = p >> 6, d = p & 63;
        s[ni][p] = Ot[(((long long)(b * HEADS + h)) * N_ + n0 + ni) * D_ + d];
    }
    __syncthreads();

    int warp = tid >> 5, lane = tid & 31;
    for (int r = warp; r < 32; r += 8) {
        float sum = 0.f, sq = 0.f;
        for (int c = lane; c < 256; c += 32) {
            float x = s[r][c];
            sum += x; sq += x * x;
        }
        #pragma unroll
        for (int o = 16; o; o >>= 1) {
            sum += __shfl_xor_sync(0xffffffffu, sum, o);
            sq  += __shfl_xor_sync(0xffffffffu, sq, o);
        }
        if (lane == 0) {
            float mu = sum * (1.0f / 256.0f);
            float var = sq * (1.0f / 256.0f) - mu * mu;
            smu[r] = mu;
            srs[r] = rsqrtf(var + 1e-6f);
        }
    }
    __syncthreads();

    // write transposed: Y[b][p][n], coalesced along n
    for (int idx = tid; idx < 32 * 256; idx += 256) {
        int ni = idx & 31;
        int p  = idx >> 5;
        float val = (s[ni][p] - smu[ni]) * srs[ni] * ln_w[p] + ln_b[p];
        Y[((long long)b * P_ + p) * N_ + n0 + ni] = val;
    }
}

// ---------------- launch ------------------------------------------------------
extern "C" void kernel_launch(void* const* d_in, const int* in_sizes, int n_in,
                              void* d_out, int out_size)
{
    const float* x     = (const float*)d_in[0];
    const float* w_ds  = (const float*)d_in[1];
    const float* wq    = (const float*)d_in[2];
    const float* bq    = (const float*)d_in[3];
    const float* wk    = (const float*)d_in[4];
    const float* bk    = (const float*)d_in[5];
    const float* wv    = (const float*)d_in[6];
    const float* bv    = (const float*)d_in[7];
    const float* rel_h = (const float*)d_in[8];
    const float* rel_w = (const float*)d_in[9];
    const float* ln_w  = (const float*)d_in[10];
    const float* ln_b  = (const float*)d_in[11];
    const float* w1    = (const float*)d_in[12];
    float* out = (float*)d_out;

    float *pBuf, *pQ, *pK, *pV, *pQp, *pKp, *pVt, *pS, *pOt, *pY;
    cudaGetSymbolAddress((void**)&pBuf, g_buf);
    cudaGetSymbolAddress((void**)&pQ,   g_q);
    cudaGetSymbolAddress((void**)&pK,   g_k);
    cudaGetSymbolAddress((void**)&pV,   g_v);
    cudaGetSymbolAddress((void**)&pQp,  g_Qp);
    cudaGetSymbolAddress((void**)&pKp,  g_Kp);
    cudaGetSymbolAddress((void**)&pVt,  g_Vt);
    cudaGetSymbolAddress((void**)&pS,   g_S);
    cudaGetSymbolAddress((void**)&pOt,  g_Ot);
    cudaGetSymbolAddress((void**)&pY,   g_Y);

    const long long sBN = (long long)P_ * N_;     // 262144
    const long long sXN = (long long)INC * N_;    // 1048576
    const long long sQP = 128LL * N_;             // 131072
    const long long sS  = (long long)N_ * N_;     // 1048576
    const long long sOT = (long long)N_ * D_;     // 65536

    // 1) downsample: g_buf = w_ds @ x   (M=256,K=1024,N=1024, batch B)
    gemm_kernel<0,0><<<dim3(8, 2, B_), 256>>>(w_ds, x, pBuf, nullptr, nullptr,
                                              P_, N_, INC, 0, sXN, sBN, 0);
    // 2) q,k,v projections (M=256,K=256,N=1024)
    gemm_kernel<0,0><<<dim3(8, 2, B_), 256>>>(wq, pBuf, pQ, bq, nullptr,
                                              P_, N_, P_, 0, sBN, sBN, 0);
    gemm_kernel<0,0><<<dim3(8, 2, B_), 256>>>(wk, pBuf, pK, bk, nullptr,
                                              P_, N_, P_, 0, sBN, sBN, 0);
    gemm_kernel<0,0><<<dim3(8, 2, B_), 256>>>(wv, pBuf, pV, bv, nullptr,
                                              P_, N_, P_, 0, sBN, sBN, 0);
    // 3) build Q' = [q;pos], K' = [k;q]; transpose V
    prep_qk<<<(B_*HEADS*128*N_ + 255) / 256, 256>>>(pQ, pK, rel_h, rel_w, pQp, pKp);
    transpose_v<<<dim3(32, 2, B_*HEADS), dim3(32, 32)>>>(pV, pVt);
    // 4) logits: S = Q'^T K'   (TN GEMM, M=N=1024, K=128, batch 64)
    gemm_kernel<1,0><<<dim3(8, 8, B_*HEADS), 256>>>(pQp, pKp, pS, nullptr, nullptr,
                                                    N_, N_, 128, sQP, sQP, sS, 0);
    // 5) softmax over rows
    softmax_kernel<<<(B_*HEADS*N_) / 8, 256>>>(pS);
    // 6) O^T = S @ V^T  (M=1024, K=1024, Ncols=64, batch 64)
    gemm_kernel<0,0><<<dim3(1, 8, B_*HEADS), 256>>>(pS, pVt, pOt, nullptr, nullptr,
                                                    N_, D_, N_, sS, sOT, sOT, 0);
    // 7) LayerNorm over channels + transpose to [b][p][n]
    ln_kernel<<<dim3(32, B_), 256>>>(pOt, ln_w, ln_b, pY);
    // 8) expand conv + exact GELU + residual -> output
    gemm_kernel<0,1><<<dim3(8, 8, B_), 256>>>(w1, pY, out, nullptr, x,
                                              INC, N_, P_, 0, sBN, sXN, sXN);
}

// round 5
// speedup vs baseline: 1.4984x; 1.4984x over previous
#include <cuda_runtime.h>
#include <math.h>

#define B_    16
#define INC   1024
#define P_    256
#define HEADS 4
#define D_    64
#define N_    1024     // W*H = 32*32
#define WW    32
#define HH    32

// ---------------- scratch (static device globals; no allocations) ----------
__device__ float g_buf[B_*P_*N_];
__device__ float g_q  [B_*P_*N_];
__device__ float g_k  [B_*P_*N_];
__device__ float g_v  [B_*P_*N_];
__device__ float g_Qp [B_*HEADS*128*N_];          // Q' = [q;pos]  [bh][dd][n]
__device__ float g_Kp [B_*HEADS*128*N_];          // K' = [k;q]    [bh][dd][n]
__device__ float g_Vt [B_*HEADS*N_*D_];           // V^T           [bh][n][d]
__device__ float g_S  [67108864];                 // logits/attn   [bh][i][j]
__device__ float g_Ot [B_*HEADS*N_*D_];           // attn out      [bh][i][d]
__device__ float g_Y  [B_*P_*N_];                 // post-LN       [b][p][n]

// ---------------- packed fp32x2 helpers (Blackwell FFMA2 path) -------------
__device__ __forceinline__ unsigned long long pk2(float lo, float hi){
    unsigned long long r;
    asm("mov.b64 %0, {%1, %2};" : "=l"(r) : "f"(lo), "f"(hi));
    return r;
}
__device__ __forceinline__ void fma2(unsigned long long &d,
                                     unsigned long long a, unsigned long long b){
    asm("fma.rn.f32x2 %0, %1, %2, %0;" : "+l"(d) : "l"(a), "l"(b));
}
__device__ __forceinline__ float2 upk2(unsigned long long v){
    float2 r;
    asm("mov.b64 {%0, %1}, %2;" : "=f"(r.x), "=f"(r.y) : "l"(v));
    return r;
}

// ---------------- tiled SGEMM v2: FFMA2 + double buffer ---------------------
// C[M][Ncols] = A * B (batched via grid.z, strides; 0 = shared operand)
// TRANS_A=0: A is [M][K]; TRANS_A=1: A is [K][M]. B is [K][Ncols].
// EPI=1: C = gelu(acc + bias) + resid.
// Requires: M % 128 == 0, Ncols % BN == 0, K % 16 == 0.
template<int TRANS_A, int EPI, int BN, int NT, int MAXB>
__global__ __launch_bounds__(NT, MAXB)
void gemm2(const float* __restrict__ A, const float* __restrict__ Bm,
           float* __restrict__ C, const float* __restrict__ bias,
           const float* __restrict__ resid,
           int M, int Ncols, int K,
           long long sA, long long sB, long long sC, long long sR)
{
    const int BM = 128, BK = 16;
    const int HALF_N = BN / 2;
    __shared__ __align__(16) float As[2][BK][BM + 4];
    __shared__ __align__(16) float Bs[2][BK][BN];

    const int bz = blockIdx.z;
    A  += sA * bz;
    Bm += sB * bz;
    C  += sC * bz;
    const float* Rp = (EPI == 1) ? resid + sR * bz : nullptr;

    const int m0 = blockIdx.y * BM;
    const int n0 = blockIdx.x * BN;
    const int tid = threadIdx.x;

    const int tx = (NT == 256) ? (tid & 15) : (tid & 7);
    const int ty = (NT == 256) ? (tid >> 4) : (tid >> 3);

    const int LA = 512 / NT;          // float4 loads per thread for A tile
    const int LB = (BN * 4) / NT;     // float4 loads per thread for B tile

    float4 aSt[LA], bSt[LB];

    unsigned long long acc[4][8];
    #pragma unroll
    for (int i = 0; i < 4; i++)
        #pragma unroll
        for (int j = 0; j < 8; j++) acc[i][j] = 0ULL;

    const int nT = K / BK;

    auto loadA = [&](int t){
        if (TRANS_A == 0){
            int r = tid >> 2, c4 = tid & 3;
            #pragma unroll
            for (int p = 0; p < LA; p++)
                aSt[p] = *reinterpret_cast<const float4*>(
                    &A[(long long)(m0 + r + p * (NT / 4)) * K + t * BK + c4 * 4]);
        } else {
            int k = tid >> 5, c = tid & 31;
            #pragma unroll
            for (int p = 0; p < LA; p++)
                aSt[p] = *reinterpret_cast<const float4*>(
                    &A[(long long)(t * BK + k + p * (NT / 32)) * M + m0 + c * 4]);
        }
    };
    auto storeA = [&](int buf){
        if (TRANS_A == 0){
            int r = tid >> 2, c4 = tid & 3;
            #pragma unroll
            for (int p = 0; p < LA; p++){
                As[buf][c4 * 4 + 0][r + p * (NT / 4)] = aSt[p].x;
                As[buf][c4 * 4 + 1][r + p * (NT / 4)] = aSt[p].y;
                As[buf][c4 * 4 + 2][r + p * (NT / 4)] = aSt[p].z;
                As[buf][c4 * 4 + 3][r + p * (NT / 4)] = aSt[p].w;
            }
        } else {
            int k = tid >> 5, c = tid & 31;
            #pragma unroll
            for (int p = 0; p < LA; p++)
                *reinterpret_cast<float4*>(&As[buf][k + p * (NT / 32)][c * 4]) = aSt[p];
        }
    };
    auto loadB = [&](int t){
        if (BN == 128){
            int k = tid >> 5, c = tid & 31;
            #pragma unroll
            for (int p = 0; p < LB; p++)
                bSt[p] = *reinterpret_cast<const float4*>(
                    &Bm[(long long)(t * BK + k + p * (NT / 32)) * Ncols + n0 + c * 4]);
        } else {
            int k = tid >> 4, c = tid & 15;
            #pragma unroll
            for (int p = 0; p < LB; p++)
                bSt[p] = *reinterpret_cast<const float4*>(
                    &Bm[(long long)(t * BK + k + p * (NT / 16)) * Ncols + n0 + c * 4]);
        }
    };
    auto storeB = [&](int buf){
        if (BN == 128){
            int k = tid >> 5, c = tid & 31;
            #pragma unroll
            for (int p = 0; p < LB; p++)
                *reinterpret_cast<float4*>(&Bs[buf][k + p * (NT / 32)][c * 4]) = bSt[p];
        } else {
            int k = tid >> 4, c = tid & 15;
            #pragma unroll
            for (int p = 0; p < LB; p++)
                *reinterpret_cast<float4*>(&Bs[buf][k + p * (NT / 16)][c * 4]) = bSt[p];
        }
    };

    loadA(0); loadB(0);
    storeA(0); storeB(0);
    __syncthreads();

    for (int t = 0; t < nT; t++){
        const int cur = t & 1;
        if (t + 1 < nT){ loadA(t + 1); loadB(t + 1); }

        #pragma unroll
        for (int kk = 0; kk < BK; kk++){
            float4 a0 = *reinterpret_cast<const float4*>(&As[cur][kk][ty * 4]);
            float4 a1 = *reinterpret_cast<const float4*>(&As[cur][kk][64 + ty * 4]);
            float4 b0 = *reinterpret_cast<const float4*>(&Bs[cur][kk][tx * 4]);
            float4 b1 = *reinterpret_cast<const float4*>(&Bs[cur][kk][HALF_N + tx * 4]);
            unsigned long long ap[4] = { pk2(a0.x, a0.y), pk2(a0.z, a0.w),
                                         pk2(a1.x, a1.y), pk2(a1.z, a1.w) };
            unsigned long long bd[8] = { pk2(b0.x, b0.x), pk2(b0.y, b0.y),
                                         pk2(b0.z, b0.z), pk2(b0.w, b0.w),
                                         pk2(b1.x, b1.x), pk2(b1.y, b1.y),
                                         pk2(b1.z, b1.z), pk2(b1.w, b1.w) };
            #pragma unroll
            for (int ip = 0; ip < 4; ip++)
                #pragma unroll
                for (int j = 0; j < 8; j++)
                    fma2(acc[ip][j], ap[ip], bd[j]);
        }

        if (t + 1 < nT){ storeA(cur ^ 1); storeB(cur ^ 1); }
        __syncthreads();
    }

    // ---- epilogue: rows r=0..7 map to (m-pair lo/hi) of acc[r>>1][*] ----
    #pragma unroll
    for (int r = 0; r < 8; r++){
        int m = m0 + ((r < 4) ? (ty * 4 + r) : (64 + ty * 4 + (r - 4)));
        float bv = bias ? bias[m] : 0.0f;
        float4 o0, o1;
        #pragma unroll
        for (int j = 0; j < 4; j++){
            float2 v = upk2(acc[r >> 1][j]);
            float2 w = upk2(acc[r >> 1][4 + j]);
            (&o0.x)[j] = ((r & 1) ? v.y : v.x) + bv;
            (&o1.x)[j] = ((r & 1) ? w.y : w.x) + bv;
        }
        long long base = (long long)m * Ncols + n0;
        if (EPI == 1){
            #pragma unroll
            for (int j = 0; j < 4; j++){
                float u0 = (&o0.x)[j], u1 = (&o1.x)[j];
                u0 = 0.5f * u0 * (1.0f + erff(u0 * 0.70710678118654752f));
                u1 = 0.5f * u1 * (1.0f + erff(u1 * 0.70710678118654752f));
                (&o0.x)[j] = u0 + Rp[base + tx * 4 + j];
                (&o1.x)[j] = u1 + Rp[base + HALF_N + tx * 4 + j];
            }
        }
        *reinterpret_cast<float4*>(&C[base + tx * 4])          = o0;
        *reinterpret_cast<float4*>(&C[base + HALF_N + tx * 4]) = o1;
    }
}

// ---------------- build Q' and K' -------------------------------------------
__global__ void prep_qk(const float* __restrict__ q, const float* __restrict__ k,
                        const float* __restrict__ rel_h, const float* __restrict__ rel_w,
                        float* __restrict__ Qp, float* __restrict__ Kp)
{
    long long idx = (long long)blockIdx.x * blockDim.x + threadIdx.x;
    if (idx >= (long long)B_ * HEADS * 128 * N_) return;
    int n  = idx & (N_ - 1);
    int dd = (idx >> 10) & 127;
    int bh = (int)(idx >> 17);
    int b = bh >> 2, h = bh & 3;

    float qv, kv;
    if (dd < D_) {
        long long src = ((long long)(b * P_ + h * D_ + dd)) * N_ + n;
        qv = q[src];
        kv = k[src];
    } else {
        int d = dd - D_;
        int w = n >> 5, hh = n & 31;
        qv = rel_h[(h * D_ + d) * HH + hh] + rel_w[(h * D_ + d) * WW + w];
        kv = q[((long long)(b * P_ + h * D_ + d)) * N_ + n];
    }
    Qp[idx] = qv;
    Kp[idx] = kv;
}

// ---------------- transpose V: [d][n] -> [n][d] per (b,h) -------------------
__global__ void transpose_v(const float* __restrict__ v, float* __restrict__ Vt)
{
    __shared__ float t[32][33];
    int bh = blockIdx.z;
    int b = bh >> 2, h = bh & 3;
    int n0 = blockIdx.x * 32;
    int d0 = blockIdx.y * 32;
    int x = threadIdx.x, y = threadIdx.y;

    t[y][x] = v[((long long)(b * P_ + h * D_ + d0 + y)) * N_ + n0 + x];
    __syncthreads();
    Vt[((long long)bh * N_ + n0 + y) * D_ + d0 + x] = t[x][y];
}

// ---------------- row softmax (warp per 1024-row) ----------------------------
__global__ void softmax_kernel(float* __restrict__ S)
{
    int gw = (blockIdx.x * blockDim.x + threadIdx.x) >> 5;
    int lane = threadIdx.x & 31;
    if (gw >= B_ * HEADS * N_) return;
    float4* row = reinterpret_cast<float4*>(S + (long long)gw * N_);

    float4 v[8];
    float mx = -1e30f;
    #pragma unroll
    for (int i = 0; i < 8; i++) {
        v[i] = row[lane + 32 * i];
        mx = fmaxf(mx, fmaxf(fmaxf(v[i].x, v[i].y), fmaxf(v[i].z, v[i].w)));
    }
    #pragma unroll
    for (int o = 16; o; o >>= 1) mx = fmaxf(mx, __shfl_xor_sync(0xffffffffu, mx, o));

    float sum = 0.0f;
    #pragma unroll
    for (int i = 0; i < 8; i++) {
        v[i].x = __expf(v[i].x - mx);
        v[i].y = __expf(v[i].y - mx);
        v[i].z = __expf(v[i].z - mx);
        v[i].w = __expf(v[i].w - mx);
        sum += v[i].x + v[i].y + v[i].z + v[i].w;
    }
    #pragma unroll
    for (int o = 16; o; o >>= 1) sum += __shfl_xor_sync(0xffffffffu, sum, o);
    float inv = 1.0f / sum;

    #pragma unroll
    for (int i = 0; i < 8; i++) {
        v[i].x *= inv; v[i].y *= inv; v[i].z *= inv; v[i].w *= inv;
        row[lane + 32 * i] = v[i];
    }
}

// ---------------- LayerNorm over channels + transpose back to [b][p][n] -----
__global__ void ln_kernel(const float* __restrict__ Ot,
                          const float* __restrict__ ln_w, const float* __restrict__ ln_b,
                          float* __restrict__ Y)
{
    __shared__ float s[32][257];
    __shared__ float smu[32], srs[32];
    int b  = blockIdx.y;
    int n0 = blockIdx.x * 32;
    int tid = threadIdx.x;

    for (int idx = tid; idx < 32 * 256; idx += 256) {
        int p  = idx & 255;
        int ni = idx >> 8;
        int h = p >> 6, d = p & 63;
        s[ni][p] = Ot[(((long long)(b * HEADS + h)) * N_ + n0 + ni) * D_ + d];
    }
    __syncthreads();

    int warp = tid >> 5, lane = tid & 31;
    for (int r = warp; r < 32; r += 8) {
        float sum = 0.f, sq = 0.f;
        for (int c = lane; c < 256; c += 32) {
            float x = s[r][c];
            sum += x; sq += x * x;
        }
        #pragma unroll
        for (int o = 16; o; o >>= 1) {
            sum += __shfl_xor_sync(0xffffffffu, sum, o);
            sq  += __shfl_xor_sync(0xffffffffu, sq, o);
        }
        if (lane == 0) {
            float mu = sum * (1.0f / 256.0f);
            float var = sq * (1.0f / 256.0f) - mu * mu;
            smu[r] = mu;
            srs[r] = rsqrtf(var + 1e-6f);
        }
    }
    __syncthreads();

    for (int idx = tid; idx < 32 * 256; idx += 256) {
        int ni = idx & 31;
        int p  = idx >> 5;
        float val = (s[ni][p] - smu[ni]) * srs[ni] * ln_w[p] + ln_b[p];
        Y[((long long)b * P_ + p) * N_ + n0 + ni] = val;
    }
}

// ---------------- launch ------------------------------------------------------
extern "C" void kernel_launch(void* const* d_in, const int* in_sizes, int n_in,
                              void* d_out, int out_size)
{
    const float* x     = (const float*)d_in[0];
    const float* w_ds  = (const float*)d_in[1];
    const float* wq    = (const float*)d_in[2];
    const float* bq    = (const float*)d_in[3];
    const float* wk    = (const float*)d_in[4];
    const float* bk    = (const float*)d_in[5];
    const float* wv    = (const float*)d_in[6];
    const float* bv    = (const float*)d_in[7];
    const float* rel_h = (const float*)d_in[8];
    const float* rel_w = (const float*)d_in[9];
    const float* ln_w  = (const float*)d_in[10];
    const float* ln_b  = (const float*)d_in[11];
    const float* w1    = (const float*)d_in[12];
    float* out = (float*)d_out;

    float *pBuf, *pQ, *pK, *pV, *pQp, *pKp, *pVt, *pS, *pOt, *pY;
    cudaGetSymbolAddress((void**)&pBuf, g_buf);
    cudaGetSymbolAddress((void**)&pQ,   g_q);
    cudaGetSymbolAddress((void**)&pK,   g_k);
    cudaGetSymbolAddress((void**)&pV,   g_v);
    cudaGetSymbolAddress((void**)&pQp,  g_Qp);
    cudaGetSymbolAddress((void**)&pKp,  g_Kp);
    cudaGetSymbolAddress((void**)&pVt,  g_Vt);
    cudaGetSymbolAddress((void**)&pS,   g_S);
    cudaGetSymbolAddress((void**)&pOt,  g_Ot);
    cudaGetSymbolAddress((void**)&pY,   g_Y);

    const long long sBN = (long long)P_ * N_;
    const long long sXN = (long long)INC * N_;
    const long long sQP = 128LL * N_;
    const long long sS  = (long long)N_ * N_;
    const long long sOT = (long long)N_ * D_;

    // 1) downsample: g_buf = w_ds @ x   (M=256,K=1024,N=1024, batch B)
    gemm2<0,0,128,256,2><<<dim3(8, 2, B_), 256>>>(w_ds, x, pBuf, nullptr, nullptr,
                                                  P_, N_, INC, 0, sXN, sBN, 0);
    // 2) q,k,v projections (M=256,K=256,N=1024)
    gemm2<0,0,128,256,2><<<dim3(8, 2, B_), 256>>>(wq, pBuf, pQ, bq, nullptr,
                                                  P_, N_, P_, 0, sBN, sBN, 0);
    gemm2<0,0,128,256,2><<<dim3(8, 2, B_), 256>>>(wk, pBuf, pK, bk, nullptr,
                                                  P_, N_, P_, 0, sBN, sBN, 0);
    gemm2<0,0,128,256,2><<<dim3(8, 2, B_), 256>>>(wv, pBuf, pV, bv, nullptr,
                                                  P_, N_, P_, 0, sBN, sBN, 0);
    // 3) build Q' = [q;pos], K' = [k;q]; transpose V
    prep_qk<<<(B_*HEADS*128*N_ + 255) / 256, 256>>>(pQ, pK, rel_h, rel_w, pQp, pKp);
    transpose_v<<<dim3(32, 2, B_*HEADS), dim3(32, 32)>>>(pV, pVt);
    // 4) logits: S = Q'^T K'   (TN GEMM, M=N=1024, K=128, batch 64)
    gemm2<1,0,128,256,2><<<dim3(8, 8, B_*HEADS), 256>>>(pQp, pKp, pS, nullptr, nullptr,
                                                        N_, N_, 128, sQP, sQP, sS, 0);
    // 5) softmax over rows
    softmax_kernel<<<(B_*HEADS*N_) / 8, 256>>>(pS);
    // 6) O^T = S @ V^T  (M=1024, Ncols=64, K=1024, batch 64) — narrow tile
    gemm2<0,0,64,128,3><<<dim3(1, 8, B_*HEADS), 128>>>(pS, pVt, pOt, nullptr, nullptr,
                                                       N_, D_, N_, sS, sOT, sOT, 0);
    // 7) LayerNorm over channels + transpose to [b][p][n]
    ln_kernel<<<dim3(32, B_), 256>>>(pOt, ln_w, ln_b, pY);
    // 8) expand conv + exact GELU + residual -> output
    gemm2<0,1,128,256,2><<<dim3(8, 8, B_), 256>>>(w1, pY, out, nullptr, x,
                                                  INC, N_, P_, 0, sBN, sXN, sXN);
}

// round 7
// speedup vs baseline: 1.5049x; 1.0044x over previous
#include <cuda_runtime.h>
#include <math.h>

#define B_    16
#define INC   1024
#define P_    256
#define HEADS 4
#define D_    64
#define N_    1024     // W*H = 32*32
#define WW    32
#define HH    32

// ---------------- scratch (static device globals; no allocations) ----------
__device__ float g_buf[B_*P_*N_];
__device__ float g_q  [B_*P_*N_];
__device__ float g_k  [B_*P_*N_];
__device__ float g_v  [B_*P_*N_];
__device__ float g_Qp [B_*HEADS*128*N_];          // Q' = [q;pos]  [bh][dd][n]
__device__ float g_Kp [B_*HEADS*128*N_];          // K' = [k;q]    [bh][dd][n]
__device__ float g_Vt [B_*HEADS*N_*D_];           // V^T           [bh][n][d]
__device__ float g_S  [67108864];                 // logits/attn   [bh][i][j]
__device__ float g_Ot [B_*HEADS*N_*D_];           // attn out      [bh][i][d]
__device__ float g_Y  [B_*P_*N_];                 // post-LN       [b][p][n]

// ---------------- packed fp32x2 helpers (Blackwell FFMA2 path) -------------
__device__ __forceinline__ unsigned long long pk2(float lo, float hi){
    unsigned long long r;
    asm("mov.b64 %0, {%1, %2};" : "=l"(r) : "f"(lo), "f"(hi));
    return r;
}
__device__ __forceinline__ void fma2(unsigned long long &d,
                                     unsigned long long a, unsigned long long b){
    asm("fma.rn.f32x2 %0, %1, %2, %0;" : "+l"(d) : "l"(a), "l"(b));
}
__device__ __forceinline__ float2 upk2(unsigned long long v){
    float2 r;
    asm("mov.b64 {%0, %1}, %2;" : "=f"(r.x), "=f"(r.y) : "l"(v));
    return r;
}

// ---------------- tiled SGEMM v2: FFMA2 + double buffer ---------------------
// C[M][Ncols] = A * B (batched via grid.z, strides; 0 = shared operand)
// TRANS_A=0: A is [M][K]; TRANS_A=1: A is [K][M]. B is [K][Ncols].
// EPI=1: C = gelu(acc + bias) + resid.
// Requires: M % 128 == 0, Ncols % BN == 0, K % 16 == 0.
template<int TRANS_A, int EPI, int BN, int NT, int MAXB>
__global__ __launch_bounds__(NT, MAXB)
void gemm2(const float* __restrict__ A, const float* __restrict__ Bm,
           float* __restrict__ C, const float* __restrict__ bias,
           const float* __restrict__ resid,
           int M, int Ncols, int K,
           long long sA, long long sB, long long sC, long long sR)
{
    const int BM = 128, BK = 16;
    const int HALF_N = BN / 2;
    __shared__ __align__(16) float As[2][BK][BM + 4];
    __shared__ __align__(16) float Bs[2][BK][BN];

    const int bz = blockIdx.z;
    A  += sA * bz;
    Bm += sB * bz;
    C  += sC * bz;
    const float* Rp = (EPI == 1) ? resid + sR * bz : nullptr;

    const int m0 = blockIdx.y * BM;
    const int n0 = blockIdx.x * BN;
    const int tid = threadIdx.x;

    const int tx = (NT == 256) ? (tid & 15) : (tid & 7);
    const int ty = (NT == 256) ? (tid >> 4) : (tid >> 3);

    const int LA = 512 / NT;          // float4 loads per thread for A tile
    const int LB = (BN * 4) / NT;     // float4 loads per thread for B tile

    float4 aSt[LA], bSt[LB];

    unsigned long long acc[4][8];
    #pragma unroll
    for (int i = 0; i < 4; i++)
        #pragma unroll
        for (int j = 0; j < 8; j++) acc[i][j] = 0ULL;

    const int nT = K / BK;

    auto loadA = [&](int t){
        if (TRANS_A == 0){
            int r = tid >> 2, c4 = tid & 3;
            #pragma unroll
            for (int p = 0; p < LA; p++)
                aSt[p] = *reinterpret_cast<const float4*>(
                    &A[(long long)(m0 + r + p * (NT / 4)) * K + t * BK + c4 * 4]);
        } else {
            int k = tid >> 5, c = tid & 31;
            #pragma unroll
            for (int p = 0; p < LA; p++)
                aSt[p] = *reinterpret_cast<const float4*>(
                    &A[(long long)(t * BK + k + p * (NT / 32)) * M + m0 + c * 4]);
        }
    };
    auto storeA = [&](int buf){
        if (TRANS_A == 0){
            int r = tid >> 2, c4 = tid & 3;
            #pragma unroll
            for (int p = 0; p < LA; p++){
                As[buf][c4 * 4 + 0][r + p * (NT / 4)] = aSt[p].x;
                As[buf][c4 * 4 + 1][r + p * (NT / 4)] = aSt[p].y;
                As[buf][c4 * 4 + 2][r + p * (NT / 4)] = aSt[p].z;
                As[buf][c4 * 4 + 3][r + p * (NT / 4)] = aSt[p].w;
            }
        } else {
            int k = tid >> 5, c = tid & 31;
            #pragma unroll
            for (int p = 0; p < LA; p++)
                *reinterpret_cast<float4*>(&As[buf][k + p * (NT / 32)][c * 4]) = aSt[p];
        }
    };
    auto loadB = [&](int t){
        if (BN == 128){
            int k = tid >> 5, c = tid & 31;
            #pragma unroll
            for (int p = 0; p < LB; p++)
                bSt[p] = *reinterpret_cast<const float4*>(
                    &Bm[(long long)(t * BK + k + p * (NT / 32)) * Ncols + n0 + c * 4]);
        } else {
            int k = tid >> 4, c = tid & 15;
            #pragma unroll
            for (int p = 0; p < LB; p++)
                bSt[p] = *reinterpret_cast<const float4*>(
                    &Bm[(long long)(t * BK + k + p * (NT / 16)) * Ncols + n0 + c * 4]);
        }
    };
    auto storeB = [&](int buf){
        if (BN == 128){
            int k = tid >> 5, c = tid & 31;
            #pragma unroll
            for (int p = 0; p < LB; p++)
                *reinterpret_cast<float4*>(&Bs[buf][k + p * (NT / 32)][c * 4]) = bSt[p];
        } else {
            int k = tid >> 4, c = tid & 15;
            #pragma unroll
            for (int p = 0; p < LB; p++)
                *reinterpret_cast<float4*>(&Bs[buf][k + p * (NT / 16)][c * 4]) = bSt[p];
        }
    };

    loadA(0); loadB(0);
    storeA(0); storeB(0);
    __syncthreads();

    for (int t = 0; t < nT; t++){
        const int cur = t & 1;
        if (t + 1 < nT){ loadA(t + 1); loadB(t + 1); }

        #pragma unroll
        for (int kk = 0; kk < BK; kk++){
            float4 a0 = *reinterpret_cast<const float4*>(&As[cur][kk][ty * 4]);
            float4 a1 = *reinterpret_cast<const float4*>(&As[cur][kk][64 + ty * 4]);
            float4 b0 = *reinterpret_cast<const float4*>(&Bs[cur][kk][tx * 4]);
            float4 b1 = *reinterpret_cast<const float4*>(&Bs[cur][kk][HALF_N + tx * 4]);
            unsigned long long ap[4] = { pk2(a0.x, a0.y), pk2(a0.z, a0.w),
                                         pk2(a1.x, a1.y), pk2(a1.z, a1.w) };
            unsigned long long bd[8] = { pk2(b0.x, b0.x), pk2(b0.y, b0.y),
                                         pk2(b0.z, b0.z), pk2(b0.w, b0.w),
                                         pk2(b1.x, b1.x), pk2(b1.y, b1.y),
                                         pk2(b1.z, b1.z), pk2(b1.w, b1.w) };
            #pragma unroll
            for (int ip = 0; ip < 4; ip++)
                #pragma unroll
                for (int j = 0; j < 8; j++)
                    fma2(acc[ip][j], ap[ip], bd[j]);
        }

        if (t + 1 < nT){ storeA(cur ^ 1); storeB(cur ^ 1); }
        __syncthreads();
    }

    // ---- epilogue: rows r=0..7 map to (m-pair lo/hi) of acc[r>>1][*] ----
    #pragma unroll
    for (int r = 0; r < 8; r++){
        int m = m0 + ((r < 4) ? (ty * 4 + r) : (64 + ty * 4 + (r - 4)));
        float bv = bias ? bias[m] : 0.0f;
        float4 o0, o1;
        #pragma unroll
        for (int j = 0; j < 4; j++){
            float2 v = upk2(acc[r >> 1][j]);
            float2 w = upk2(acc[r >> 1][4 + j]);
            (&o0.x)[j] = ((r & 1) ? v.y : v.x) + bv;
            (&o1.x)[j] = ((r & 1) ? w.y : w.x) + bv;
        }
        long long base = (long long)m * Ncols + n0;
        if (EPI == 1){
            #pragma unroll
            for (int j = 0; j < 4; j++){
                float u0 = (&o0.x)[j], u1 = (&o1.x)[j];
                u0 = 0.5f * u0 * (1.0f + erff(u0 * 0.70710678118654752f));
                u1 = 0.5f * u1 * (1.0f + erff(u1 * 0.70710678118654752f));
                (&o0.x)[j] = u0 + Rp[base + tx * 4 + j];
                (&o1.x)[j] = u1 + Rp[base + HALF_N + tx * 4 + j];
            }
        }
        *reinterpret_cast<float4*>(&C[base + tx * 4])          = o0;
        *reinterpret_cast<float4*>(&C[base + HALF_N + tx * 4]) = o1;
    }
}

// ---------------- build Q' and K' -------------------------------------------
__global__ void prep_qk(const float* __restrict__ q, const float* __restrict__ k,
                        const float* __restrict__ rel_h, const float* __restrict__ rel_w,
                        float* __restrict__ Qp, float* __restrict__ Kp)
{
    long long idx = (long long)blockIdx.x * blockDim.x + threadIdx.x;
    if (idx >= (long long)B_ * HEADS * 128 * N_) return;
    int n  = idx & (N_ - 1);
    int dd = (idx >> 10) & 127;
    int bh = (int)(idx >> 17);
    int b = bh >> 2, h = bh & 3;

    float qv, kv;
    if (dd < D_) {
        long long src = ((long long)(b * P_ + h * D_ + dd)) * N_ + n;
        qv = q[src];
        kv = k[src];
    } else {
        int d = dd - D_;
        int w = n >> 5, hh = n & 31;
        qv = rel_h[(h * D_ + d) * HH + hh] + rel_w[(h * D_ + d) * WW + w];
        kv = q[((long long)(b * P_ + h * D_ + d)) * N_ + n];
    }
    Qp[idx] = qv;
    Kp[idx] = kv;
}

// ---------------- transpose V: [d][n] -> [n][d] per (b,h) -------------------
__global__ void transpose_v(const float* __restrict__ v, float* __restrict__ Vt)
{
    __shared__ float t[32][33];
    int bh = blockIdx.z;
    int b = bh >> 2, h = bh & 3;
    int n0 = blockIdx.x * 32;
    int d0 = blockIdx.y * 32;
    int x = threadIdx.x, y = threadIdx.y;

    t[y][x] = v[((long long)(b * P_ + h * D_ + d0 + y)) * N_ + n0 + x];
    __syncthreads();
    Vt[((long long)bh * N_ + n0 + y) * D_ + d0 + x] = t[x][y];
}

// ---------------- row softmax (warp per 1024-row) ----------------------------
__global__ void softmax_kernel(float* __restrict__ S)
{
    int gw = (blockIdx.x * blockDim.x + threadIdx.x) >> 5;
    int lane = threadIdx.x & 31;
    if (gw >= B_ * HEADS * N_) return;
    float4* row = reinterpret_cast<float4*>(S + (long long)gw * N_);

    float4 v[8];
    float mx = -1e30f;
    #pragma unroll
    for (int i = 0; i < 8; i++) {
        v[i] = row[lane + 32 * i];
        mx = fmaxf(mx, fmaxf(fmaxf(v[i].x, v[i].y), fmaxf(v[i].z, v[i].w)));
    }
    #pragma unroll
    for (int o = 16; o; o >>= 1) mx = fmaxf(mx, __shfl_xor_sync(0xffffffffu, mx, o));

    float sum = 0.0f;
    #pragma unroll
    for (int i = 0; i < 8; i++) {
        v[i].x = __expf(v[i].x - mx);
        v[i].y = __expf(v[i].y - mx);
        v[i].z = __expf(v[i].z - mx);
        v[i].w = __expf(v[i].w - mx);
        sum += v[i].x + v[i].y + v[i].z + v[i].w;
    }
    #pragma unroll
    for (int o = 16; o; o >>= 1) sum += __shfl_xor_sync(0xffffffffu, sum, o);
    float inv = 1.0f / sum;

    #pragma unroll
    for (int i = 0; i < 8; i++) {
        v[i].x *= inv; v[i].y *= inv; v[i].z *= inv; v[i].w *= inv;
        row[lane + 32 * i] = v[i];
    }
}

// ---------------- LayerNorm over channels + transpose back to [b][p][n] -----
__global__ void ln_kernel(const float* __restrict__ Ot,
                          const float* __restrict__ ln_w, const float* __restrict__ ln_b,
                          float* __restrict__ Y)
{
    __shared__ float s[32][257];
    __shared__ float smu[32], srs[32];
    int b  = blockIdx.y;
    int n0 = blockIdx.x * 32;
    int tid = threadIdx.x;

    for (int idx = tid; idx < 32 * 256; idx += 256) {
        int p  = idx & 255;
        int ni = idx >> 8;
        int h = p >> 6, d = p & 63;
        s[ni][p] = Ot[(((long long)(b * HEADS + h)) * N_ + n0 + ni) * D_ + d];
    }
    __syncthreads();

    int warp = tid >> 5, lane = tid & 31;
    for (int r = warp; r < 32; r += 8) {
        float sum = 0.f, sq = 0.f;
        for (int c = lane; c < 256; c += 32) {
            float x = s[r][c];
            sum += x; sq += x * x;
        }
        #pragma unroll
        for (int o = 16; o; o >>= 1) {
            sum += __shfl_xor_sync(0xffffffffu, sum, o);
            sq  += __shfl_xor_sync(0xffffffffu, sq, o);
        }
        if (lane == 0) {
            float mu = sum * (1.0f / 256.0f);
            float var = sq * (1.0f / 256.0f) - mu * mu;
            smu[r] = mu;
            srs[r] = rsqrtf(var + 1e-6f);
        }
    }
    __syncthreads();

    for (int idx = tid; idx < 32 * 256; idx += 256) {
        int ni = idx & 31;
        int p  = idx >> 5;
        float val = (s[ni][p] - smu[ni]) * srs[ni] * ln_w[p] + ln_b[p];
        Y[((long long)b * P_ + p) * N_ + n0 + ni] = val;
    }
}

// ---------------- launch ------------------------------------------------------
extern "C" void kernel_launch(void* const* d_in, const int* in_sizes, int n_in,
                              void* d_out, int out_size)
{
    const float* x     = (const float*)d_in[0];
    const float* w_ds  = (const float*)d_in[1];
    const float* wq    = (const float*)d_in[2];
    const float* bq    = (const float*)d_in[3];
    const float* wk    = (const float*)d_in[4];
    const float* bk    = (const float*)d_in[5];
    const float* wv    = (const float*)d_in[6];
    const float* bv    = (const float*)d_in[7];
    const float* rel_h = (const float*)d_in[8];
    const float* rel_w = (const float*)d_in[9];
    const float* ln_w  = (const float*)d_in[10];
    const float* ln_b  = (const float*)d_in[11];
    const float* w1    = (const float*)d_in[12];
    float* out = (float*)d_out;

    float *pBuf, *pQ, *pK, *pV, *pQp, *pKp, *pVt, *pS, *pOt, *pY;
    cudaGetSymbolAddress((void**)&pBuf, g_buf);
    cudaGetSymbolAddress((void**)&pQ,   g_q);
    cudaGetSymbolAddress((void**)&pK,   g_k);
    cudaGetSymbolAddress((void**)&pV,   g_v);
    cudaGetSymbolAddress((void**)&pQp,  g_Qp);
    cudaGetSymbolAddress((void**)&pKp,  g_Kp);
    cudaGetSymbolAddress((void**)&pVt,  g_Vt);
    cudaGetSymbolAddress((void**)&pS,   g_S);
    cudaGetSymbolAddress((void**)&pOt,  g_Ot);
    cudaGetSymbolAddress((void**)&pY,   g_Y);

    const long long sBN = (long long)P_ * N_;
    const long long sXN = (long long)INC * N_;
    const long long sQP = 128LL * N_;
    const long long sS  = (long long)N_ * N_;
    const long long sOT = (long long)N_ * D_;

    // 1) downsample: g_buf = w_ds @ x   (M=256,K=1024,N=1024, batch B)
    gemm2<0,0,128,256,2><<<dim3(8, 2, B_), 256>>>(w_ds, x, pBuf, nullptr, nullptr,
                                                  P_, N_, INC, 0, sXN, sBN, 0);
    // 2) q,k,v projections (M=256,K=256,N=1024)
    gemm2<0,0,128,256,2><<<dim3(8, 2, B_), 256>>>(wq, pBuf, pQ, bq, nullptr,
                                                  P_, N_, P_, 0, sBN, sBN, 0);
    gemm2<0,0,128,256,2><<<dim3(8, 2, B_), 256>>>(wk, pBuf, pK, bk, nullptr,
                                                  P_, N_, P_, 0, sBN, sBN, 0);
    gemm2<0,0,128,256,2><<<dim3(8, 2, B_), 256>>>(wv, pBuf, pV, bv, nullptr,
                                                  P_, N_, P_, 0, sBN, sBN, 0);
    // 3) build Q' = [q;pos], K' = [k;q]; transpose V
    prep_qk<<<(B_*HEADS*128*N_ + 255) / 256, 256>>>(pQ, pK, rel_h, rel_w, pQp, pKp);
    transpose_v<<<dim3(32, 2, B_*HEADS), dim3(32, 32)>>>(pV, pVt);
    // 4) logits: S = Q'^T K'   (TN GEMM, M=N=1024, K=128, batch 64)
    gemm2<1,0,128,256,2><<<dim3(8, 8, B_*HEADS), 256>>>(pQp, pKp, pS, nullptr, nullptr,
                                                        N_, N_, 128, sQP, sQP, sS, 0);
    // 5) softmax over rows
    softmax_kernel<<<(B_*HEADS*N_) / 8, 256>>>(pS);
    // 6) O^T = S @ V^T  (M=1024, Ncols=64, K=1024, batch 64) — narrow tile
    gemm2<0,0,64,128,3><<<dim3(1, 8, B_*HEADS), 128>>>(pS, pVt, pOt, nullptr, nullptr,
                                                       N_, D_, N_, sS, sOT, sOT, 0);
    // 7) LayerNorm over channels + transpose to [b][p][n]
    ln_kernel<<<dim3(32, B_), 256>>>(pOt, ln_w, ln_b, pY);
    // 8) expand conv + exact GELU + residual -> output
    gemm2<0,1,128,256,2><<<dim3(8, 8, B_), 256>>>(w1, pY, out, nullptr, x,
                                                  INC, N_, P_, 0, sBN, sXN, sXN);
}

// round 10
// speedup vs baseline: 1.5267x; 1.0145x over previous
#include <cuda_runtime.h>
#include <cuda_bf16.h>
#include <math.h>
#include <stdint.h>

#define B_    16
#define INC   1024
#define P_    256
#define HEADS 4
#define D_    64
#define N_    1024
#define WW    32
#define HH    32

typedef __nv_bfloat16 bf16;

// ---------------- scratch (static device globals) ---------------------------
__device__ bf16  g_wds2[256*2048];
__device__ bf16  g_wq2 [256*512];
__device__ bf16  g_wk2 [256*512];
__device__ bf16  g_wv2 [256*512];
__device__ bf16  g_w12 [1024*512];
__device__ bf16  g_xT  [16LL*1024*2048];   // [b][n][hi c|lo c]
__device__ float g_buf [16*256*1024];      // downsample out fp32 [b][p][n]
__device__ bf16  g_bufT[16LL*1024*512];    // [b][n][hi p|lo p]
__device__ float g_q   [16*256*1024];
__device__ float g_k   [16*256*1024];
__device__ float g_v   [16*256*1024];
__device__ bf16  g_V2  [16LL*256*2048];    // [b][p][hi j|lo j]
__device__ bf16  g_QpT [64LL*1024*256];    // [bh][n][hi dd|lo dd]
__device__ bf16  g_KpT [64LL*1024*256];
__device__ float g_S   [64LL*1024*1024];
__device__ bf16  g_P   [64LL*1024*2048];   // [bh][i][hi j|lo j]
__device__ float g_Ot  [64LL*1024*64];
__device__ bf16  g_yT  [16LL*1024*512];    // [b][n][hi p|lo p]

__device__ __forceinline__ void split2(float v, bf16& hi, bf16& lo){
    hi = __float2bfloat16(v);
    lo = __float2bfloat16(v - __bfloat162float(hi));
}

// ---------------- mma.sync split-bf16 batched GEMM ---------------------------
// D[M][Ncols] = A * B^T over 3 bf16 segments (hi.hi, lo.hi, hi.lo).
// A: [M][lda] bf16 rows = hi[0..Kseg) | lo[Kseg..2Kseg). B: [Ncols][ldb] same.
// EPI 0: C = D (+bias). EPI 1: C = gelu(D) + resid.
template<int BN, int EPI>
__global__ __launch_bounds__(256)
void mma_gemm(const bf16* __restrict__ A, const bf16* __restrict__ Bm,
              float* __restrict__ C,
              const float* __restrict__ bias, const float* __restrict__ resid,
              int Kseg, long long sA, long long sB, long long sC,
              int lda, int ldb, int ldc)
{
    const int BM = 128, BK = 32;
    const int WN = BN / 2;          // warp n-tile: 64 or 32
    const int NTL = WN / 8;         // n mma tiles per warp: 8 or 4
    const int SAP = 40;             // smem row stride in bf16 (80B, conflict-free)
    __shared__ __align__(16) bf16 As[2][BM * SAP];
    __shared__ __align__(16) bf16 Bs[2][BN * SAP];

    const int tid = threadIdx.x, wid = tid >> 5, lane = tid & 31;
    const int wy = wid & 3, wx = wid >> 2;          // 4 x 2 warp grid
    const int bz = blockIdx.z;
    A  += sA * bz;
    Bm += sB * bz;
    C  += sC * bz;
    const float* Rp = (EPI == 1) ? resid + sC * bz : nullptr;
    const int m0 = blockIdx.y * BM;
    const int n0 = blockIdx.x * BN;

    float acc[2][NTL][4];
    #pragma unroll
    for (int i = 0; i < 2; i++)
        #pragma unroll
        for (int j = 0; j < NTL; j++)
            #pragma unroll
            for (int t = 0; t < 4; t++) acc[i][j][t] = 0.0f;

    const int cps = Kseg >> 5;      // 32-wide chunks per segment
    const int NC  = 3 * cps;

    const int rowA  = tid >> 1, halfA = tid & 1;    // A & B(BN=128): 2 thr/row
    const int rowB4 = tid >> 2, qB = tid & 3;       // B(BN=64): 4 thr/row

    uint4 ra[2], rb[2];

    auto ldg = [&](int c){
        int seg = c / cps, ck = c - seg * cps;
        long long kA = (long long)((seg == 1) ? Kseg : 0) + ck * 32;
        long long kB = (long long)((seg == 2) ? Kseg : 0) + ck * 32;
        const uint4* pa = reinterpret_cast<const uint4*>(
            &A[(long long)(m0 + rowA) * lda + kA + halfA * 16]);
        ra[0] = pa[0]; ra[1] = pa[1];
        if (BN == 128){
            const uint4* pb = reinterpret_cast<const uint4*>(
                &Bm[(long long)(n0 + rowA) * ldb + kB + halfA * 16]);
            rb[0] = pb[0]; rb[1] = pb[1];
        } else {
            const uint4* pb = reinterpret_cast<const uint4*>(
                &Bm[(long long)(n0 + rowB4) * ldb + kB + qB * 8]);
            rb[0] = pb[0];
        }
    };
    auto stg = [&](int buf){
        *reinterpret_cast<uint4*>(&As[buf][rowA * SAP + halfA * 16])     = ra[0];
        *reinterpret_cast<uint4*>(&As[buf][rowA * SAP + halfA * 16 + 8]) = ra[1];
        if (BN == 128){
            *reinterpret_cast<uint4*>(&Bs[buf][rowA * SAP + halfA * 16])     = rb[0];
            *reinterpret_cast<uint4*>(&Bs[buf][rowA * SAP + halfA * 16 + 8]) = rb[1];
        } else {
            *reinterpret_cast<uint4*>(&Bs[buf][rowB4 * SAP + qB * 8]) = rb[0];
        }
    };
    auto compute = [&](int buf){
        const bf16* as = As[buf];
        const bf16* bs = Bs[buf];
        #pragma unroll
        for (int kt = 0; kt < 2; kt++){
            const int kb = kt * 16 + (lane & 3) * 2;
            uint32_t af[2][4];
            #pragma unroll
            for (int mt = 0; mt < 2; mt++){
                const bf16* ab = as + (wy * 32 + mt * 16 + (lane >> 2)) * SAP + kb;
                af[mt][0] = *reinterpret_cast<const uint32_t*>(ab);
                af[mt][1] = *reinterpret_cast<const uint32_t*>(ab + 8 * SAP);
                af[mt][2] = *reinterpret_cast<const uint32_t*>(ab + 8);
                af[mt][3] = *reinterpret_cast<const uint32_t*>(ab + 8 * SAP + 8);
            }
            #pragma unroll
            for (int nt = 0; nt < NTL; nt++){
                const bf16* bb = bs + (wx * WN + nt * 8 + (lane >> 2)) * SAP + kb;
                uint32_t b0 = *reinterpret_cast<const uint32_t*>(bb);
                uint32_t b1 = *reinterpret_cast<const uint32_t*>(bb + 8);
                #pragma unroll
                for (int mt = 0; mt < 2; mt++){
                    asm volatile(
                        "mma.sync.aligned.m16n8k16.row.col.f32.bf16.bf16.f32 "
                        "{%0,%1,%2,%3}, {%4,%5,%6,%7}, {%8,%9}, {%0,%1,%2,%3};"
                        : "+f"(acc[mt][nt][0]), "+f"(acc[mt][nt][1]),
                          "+f"(acc[mt][nt][2]), "+f"(acc[mt][nt][3])
                        : "r"(af[mt][0]), "r"(af[mt][1]), "r"(af[mt][2]), "r"(af[mt][3]),
                          "r"(b0), "r"(b1));
                }
            }
        }
    };

    ldg(0); stg(0);
    __syncthreads();
    for (int c = 0; c < NC; c++){
        const int cur = c & 1;
        if (c + 1 < NC) ldg(c + 1);
        compute(cur);
        if (c + 1 < NC) stg(cur ^ 1);
        __syncthreads();
    }

    // ---- epilogue ----
    #pragma unroll
    for (int mt = 0; mt < 2; mt++){
        const int r0 = m0 + wy * 32 + mt * 16 + (lane >> 2);
        const float bv0 = bias ? bias[r0] : 0.0f;
        const float bv8 = bias ? bias[r0 + 8] : 0.0f;
        #pragma unroll
        for (int nt = 0; nt < NTL; nt++){
            const int cIdx = n0 + wx * WN + nt * 8 + (lane & 3) * 2;
            float v0 = acc[mt][nt][0] + bv0, v1 = acc[mt][nt][1] + bv0;
            float v2 = acc[mt][nt][2] + bv8, v3 = acc[mt][nt][3] + bv8;
            const long long o0 = (long long)r0 * ldc + cIdx;
            const long long o8 = (long long)(r0 + 8) * ldc + cIdx;
            if (EPI == 1){
                v0 = 0.5f * v0 * (1.0f + erff(v0 * 0.70710678118654752f)) + Rp[o0];
                v1 = 0.5f * v1 * (1.0f + erff(v1 * 0.70710678118654752f)) + Rp[o0 + 1];
                v2 = 0.5f * v2 * (1.0f + erff(v2 * 0.70710678118654752f)) + Rp[o8];
                v3 = 0.5f * v3 * (1.0f + erff(v3 * 0.70710678118654752f)) + Rp[o8 + 1];
            }
            *reinterpret_cast<float2*>(&C[o0]) = make_float2(v0, v1);
            *reinterpret_cast<float2*>(&C[o8]) = make_float2(v2, v3);
        }
    }
}

// ---------------- elementwise prep kernels ----------------------------------
// row-major split: src rows of length K -> dst rows [hi K | lo K]
__global__ void split_w(const float* __restrict__ src, bf16* __restrict__ dst,
                        int K, int total)
{
    int idx = blockIdx.x * blockDim.x + threadIdx.x;
    if (idx >= total) return;
    int mrow = idx / K, k = idx - mrow * K;
    bf16 hi, lo; split2(src[idx], hi, lo);
    long long b = (long long)mrow * 2 * K + k;
    dst[b] = hi;
    dst[b + K] = lo;
}

// transpose+split: src [b][C][1024] -> dst [b][n][ldDst] hi @ c, lo @ c+loOff
__global__ void splitT(const float* __restrict__ src, bf16* __restrict__ dst,
                       int Cch, int ldDst, int loOff)
{
    __shared__ float sh[32][33];
    int b = blockIdx.z, n0 = blockIdx.x * 32, c0 = blockIdx.y * 32;
    int tx = threadIdx.x, ty = threadIdx.y;
    sh[ty][tx] = src[((long long)b * Cch + c0 + ty) * N_ + n0 + tx];
    __syncthreads();
    bf16 hi, lo; split2(sh[tx][ty], hi, lo);
    long long base = ((long long)b * N_ + n0 + ty) * ldDst + c0 + tx;
    dst[base] = hi;
    dst[base + loOff] = lo;
}

__global__ void prep_qkT(const float* __restrict__ q, const float* __restrict__ k,
                         const float* __restrict__ rel_h, const float* __restrict__ rel_w,
                         bf16* __restrict__ QpT, bf16* __restrict__ KpT)
{
    __shared__ float sq[32][33], sk[32][33];
    int bh = blockIdx.z, b = bh >> 2, h = bh & 3;
    int n0 = blockIdx.x * 32, dd0 = blockIdx.y * 32;
    int tx = threadIdx.x, ty = threadIdx.y;
    int dd = dd0 + ty, n = n0 + tx;
    float qv, kv;
    if (dd < 64){
        long long src = ((long long)(b * P_ + h * D_ + dd)) * N_ + n;
        qv = q[src]; kv = k[src];
    } else {
        int d = dd - 64;
        int w = n >> 5, hh = n & 31;
        qv = rel_h[(h * D_ + d) * HH + hh] + rel_w[(h * D_ + d) * WW + w];
        kv = q[((long long)(b * P_ + h * D_ + d)) * N_ + n];
    }
    sq[ty][tx] = qv; sk[ty][tx] = kv;
    __syncthreads();
    long long base = ((long long)bh * N_ + n0 + ty) * 256 + dd0 + tx;
    bf16 hi, lo;
    split2(sq[tx][ty], hi, lo); QpT[base] = hi; QpT[base + 128] = lo;
    split2(sk[tx][ty], hi, lo); KpT[base] = hi; KpT[base + 128] = lo;
}

__global__ void softmax_split(const float* __restrict__ S, bf16* __restrict__ P)
{
    int gw = (blockIdx.x * blockDim.x + threadIdx.x) >> 5;
    int lane = threadIdx.x & 31;
    if (gw >= B_ * HEADS * N_) return;
    const float4* row = reinterpret_cast<const float4*>(S + (long long)gw * N_);

    float4 v[8];
    float mx = -1e30f;
    #pragma unroll
    for (int i = 0; i < 8; i++){
        v[i] = row[lane + 32 * i];
        mx = fmaxf(mx, fmaxf(fmaxf(v[i].x, v[i].y), fmaxf(v[i].z, v[i].w)));
    }
    #pragma unroll
    for (int o = 16; o; o >>= 1) mx = fmaxf(mx, __shfl_xor_sync(0xffffffffu, mx, o));
    float sum = 0.f;
    #pragma unroll
    for (int i = 0; i < 8; i++){
        v[i].x = __expf(v[i].x - mx); v[i].y = __expf(v[i].y - mx);
        v[i].z = __expf(v[i].z - mx); v[i].w = __expf(v[i].w - mx);
        sum += v[i].x + v[i].y + v[i].z + v[i].w;
    }
    #pragma unroll
    for (int o = 16; o; o >>= 1) sum += __shfl_xor_sync(0xffffffffu, sum, o);
    float inv = 1.0f / sum;

    __nv_bfloat162* ph = reinterpret_cast<__nv_bfloat162*>(P + (long long)gw * 2048);
    __nv_bfloat162* pl = reinterpret_cast<__nv_bfloat162*>(P + (long long)gw * 2048 + 1024);
    #pragma unroll
    for (int i = 0; i < 8; i++){
        float a = v[i].x * inv, bb = v[i].y * inv, cf = v[i].z * inv, df = v[i].w * inv;
        bf16 ha, hb, hc, hd, la, lb, lc, ld;
        split2(a, ha, la); split2(bb, hb, lb); split2(cf, hc, lc); split2(df, hd, ld);
        int j4 = lane + 32 * i;
        ph[2 * j4]     = __nv_bfloat162(ha, hb);
        ph[2 * j4 + 1] = __nv_bfloat162(hc, hd);
        pl[2 * j4]     = __nv_bfloat162(la, lb);
        pl[2 * j4 + 1] = __nv_bfloat162(lc, ld);
    }
}

__global__ void ln_yT(const float* __restrict__ Ot,
                      const float* __restrict__ ln_w, const float* __restrict__ ln_b,
                      bf16* __restrict__ yT)
{
    __shared__ float s[32][257];
    __shared__ float smu[32], srs[32];
    int b  = blockIdx.y;
    int n0 = blockIdx.x * 32;
    int tid = threadIdx.x;

    for (int idx = tid; idx < 32 * 256; idx += 256){
        int p  = idx & 255;
        int ni = idx >> 8;
        int h = p >> 6, d = p & 63;
        s[ni][p] = Ot[(((long long)(b * HEADS + h)) * N_ + n0 + ni) * D_ + d];
    }
    __syncthreads();

    int warp = tid >> 5, lane = tid & 31;
    for (int r = warp; r < 32; r += 8){
        float sum = 0.f, sq = 0.f;
        for (int c = lane; c < 256; c += 32){
            float xv = s[r][c];
            sum += xv; sq += xv * xv;
        }
        #pragma unroll
        for (int o = 16; o; o >>= 1){
            sum += __shfl_xor_sync(0xffffffffu, sum, o);
            sq  += __shfl_xor_sync(0xffffffffu, sq, o);
        }
        if (lane == 0){
            float mu = sum * (1.0f / 256.0f);
            float var = sq * (1.0f / 256.0f) - mu * mu;
            smu[r] = mu;
            srs[r] = rsqrtf(var + 1e-6f);
        }
    }
    __syncthreads();

    for (int idx = tid; idx < 32 * 256; idx += 256){
        int p  = idx & 255;
        int ni = idx >> 8;
        float val = (s[ni][p] - smu[ni]) * srs[ni] * ln_w[p] + ln_b[p];
        bf16 hi, lo; split2(val, hi, lo);
        long long base = ((long long)b * N_ + n0 + ni) * 512 + p;
        yT[base] = hi;
        yT[base + 256] = lo;
    }
}

// ---------------- launch -------------------------------------------------------
extern "C" void kernel_launch(void* const* d_in, const int* in_sizes, int n_in,
                              void* d_out, int out_size)
{
    const float* x     = (const float*)d_in[0];
    const float* w_ds  = (const float*)d_in[1];
    const float* wq    = (const float*)d_in[2];
    const float* bq    = (const float*)d_in[3];
    const float* wk    = (const float*)d_in[4];
    const float* bk    = (const float*)d_in[5];
    const float* wv    = (const float*)d_in[6];
    const float* bv    = (const float*)d_in[7];
    const float* rel_h = (const float*)d_in[8];
    const float* rel_w = (const float*)d_in[9];
    const float* ln_w  = (const float*)d_in[10];
    const float* ln_b  = (const float*)d_in[11];
    const float* w1    = (const float*)d_in[12];
    float* out = (float*)d_out;

    bf16 *pWds, *pWq, *pWk, *pWv, *pW1, *pXT, *pBufT, *pV2, *pQpT, *pKpT, *pP, *pYT;
    float *pBuf, *pQ, *pK, *pV, *pS, *pOt;
    cudaGetSymbolAddress((void**)&pWds, g_wds2);
    cudaGetSymbolAddress((void**)&pWq,  g_wq2);
    cudaGetSymbolAddress((void**)&pWk,  g_wk2);
    cudaGetSymbolAddress((void**)&pWv,  g_wv2);
    cudaGetSymbolAddress((void**)&pW1,  g_w12);
    cudaGetSymbolAddress((void**)&pXT,  g_xT);
    cudaGetSymbolAddress((void**)&pBuf, g_buf);
    cudaGetSymbolAddress((void**)&pBufT,g_bufT);
    cudaGetSymbolAddress((void**)&pQ,   g_q);
    cudaGetSymbolAddress((void**)&pK,   g_k);
    cudaGetSymbolAddress((void**)&pV,   g_v);
    cudaGetSymbolAddress((void**)&pV2,  g_V2);
    cudaGetSymbolAddress((void**)&pQpT, g_QpT);
    cudaGetSymbolAddress((void**)&pKpT, g_KpT);
    cudaGetSymbolAddress((void**)&pS,   g_S);
    cudaGetSymbolAddress((void**)&pP,   g_P);
    cudaGetSymbolAddress((void**)&pOt,  g_Ot);
    cudaGetSymbolAddress((void**)&pYT,  g_yT);

    // 0) weight + input splits
    split_w<<<(256*1024 + 255)/256, 256>>>(w_ds, pWds, 1024, 256*1024);
    split_w<<<(256*256  + 255)/256, 256>>>(wq, pWq, 256, 256*256);
    split_w<<<(256*256  + 255)/256, 256>>>(wk, pWk, 256, 256*256);
    split_w<<<(256*256  + 255)/256, 256>>>(wv, pWv, 256, 256*256);
    split_w<<<(1024*256 + 255)/256, 256>>>(w1, pW1, 256, 1024*256);
    splitT<<<dim3(32, 32, B_), dim3(32, 32)>>>(x, pXT, 1024, 2048, 1024);

    // 1) downsample: buf = w_ds @ x   (M=256, N=1024, Kseg=1024)
    mma_gemm<128,0><<<dim3(8, 2, B_), 256>>>(pWds, pXT, pBuf, nullptr, nullptr,
        1024, 0, 1024LL*2048, 256LL*1024, 2048, 2048, 1024);
    splitT<<<dim3(32, 8, B_), dim3(32, 32)>>>(pBuf, pBufT, 256, 512, 256);

    // 2) q, k, v projections (M=256, N=1024, Kseg=256)
    mma_gemm<128,0><<<dim3(8, 2, B_), 256>>>(pWq, pBufT, pQ, bq, nullptr,
        256, 0, 1024LL*512, 256LL*1024, 512, 512, 1024);
    mma_gemm<128,0><<<dim3(8, 2, B_), 256>>>(pWk, pBufT, pK, bk, nullptr,
        256, 0, 1024LL*512, 256LL*1024, 512, 512, 1024);
    mma_gemm<128,0><<<dim3(8, 2, B_), 256>>>(pWv, pBufT, pV, bv, nullptr,
        256, 0, 1024LL*512, 256LL*1024, 512, 512, 1024);
    split_w<<<(16*256*1024 + 255)/256, 256>>>(pV, pV2, 1024, 16*256*1024);

    // 3) Qp^T / Kp^T (split, n-major)
    prep_qkT<<<dim3(32, 4, B_*HEADS), dim3(32, 32)>>>(pQ, pK, rel_h, rel_w, pQpT, pKpT);

    // 4) logits S = Qp^T . Kp  (M=1024, N=1024, Kseg=128, batch 64)
    mma_gemm<128,0><<<dim3(8, 8, B_*HEADS), 256>>>(pQpT, pKpT, pS, nullptr, nullptr,
        128, 1024LL*256, 1024LL*256, 1024LL*1024, 256, 256, 1024);

    // 5) softmax -> split probs
    softmax_split<<<(B_*HEADS*N_) / 8, 256>>>(pS, pP);

    // 6) Ot = P . V^T  (M=1024, N=64, Kseg=1024, batch 64; B strided per head)
    mma_gemm<64,0><<<dim3(1, 8, B_*HEADS), 256>>>(pP, pV2, pOt, nullptr, nullptr,
        1024, 1024LL*2048, 64LL*2048, 1024LL*64, 2048, 2048, 64);

    // 7) LayerNorm -> y^T split
    ln_yT<<<dim3(32, B_), 256>>>(pOt, ln_w, ln_b, pYT);

    // 8) expand + exact GELU + residual (M=1024, N=1024, Kseg=256)
    mma_gemm<128,1><<<dim3(8, 8, B_), 256>>>(pW1, pYT, out, nullptr, x,
        256, 0, 1024LL*512, 1024LL*1024, 512, 512, 1024);
}

// round 11
// speedup vs baseline: 2.1152x; 1.3855x over previous
#include <cuda_runtime.h>
#include <cuda_bf16.h>
#include <math.h>
#include <stdint.h>

#define B_    16
#define INC   1024
#define P_    256
#define HEADS 4
#define D_    64
#define N_    1024
#define WW    32
#define HH    32

typedef __nv_bfloat16 bf16;

// ---------------- scratch (static device globals) ---------------------------
__device__ bf16  g_wds2 [256*2048];
__device__ bf16  g_wqkv2[768*512];
__device__ float g_bqkv [768];
__device__ bf16  g_w12  [1024*512];
__device__ bf16  g_xT   [16LL*1024*2048];   // [b][n][hi c|lo c]
__device__ float g_buf  [16*256*1024];      // downsample out fp32 [b][p][n]
__device__ bf16  g_bufT [16LL*1024*512];    // [b][n][hi p|lo p]
__device__ float g_qkv  [16LL*768*1024];    // q rows 0-255, k 256-511, v 512-767
__device__ bf16  g_V2   [16LL*256*2048];    // [b][p][hi j|lo j]
__device__ bf16  g_QpT  [64LL*1024*256];    // [bh][n][hi dd|lo dd]
__device__ bf16  g_KpT  [64LL*1024*256];
__device__ float g_S    [64LL*1024*1024];
__device__ bf16  g_P    [64LL*1024*2048];   // [bh][i][hi j|lo j]
__device__ float g_Ot   [64LL*1024*64];
__device__ bf16  g_yT   [16LL*1024*512];    // [b][n][hi p|lo p]

__device__ __forceinline__ void split2(float v, bf16& hi, bf16& lo){
    hi = __float2bfloat16(v);
    lo = __float2bfloat16(v - __bfloat162float(hi));
}
__device__ __forceinline__ uint32_t smem_u32(const void* p){
    uint32_t a;
    asm("{ .reg .u64 t; cvta.to.shared.u64 t, %1; cvt.u32.u64 %0, t; }" : "=r"(a) : "l"(p));
    return a;
}
__device__ __forceinline__ void cpa16(uint32_t s, const void* g){
    asm volatile("cp.async.cg.shared.global [%0], [%1], 16;" :: "r"(s), "l"(g));
}
#define CP_COMMIT() asm volatile("cp.async.commit_group;" ::: "memory")
#define CP_WAIT1()  asm volatile("cp.async.wait_group 1;" ::: "memory")
#define CP_WAIT0()  asm volatile("cp.async.wait_group 0;" ::: "memory")
#define LDSM_X4(r, a) \
    asm volatile("ldmatrix.sync.aligned.m8n8.x4.shared.b16 {%0,%1,%2,%3}, [%4];" \
        : "=r"((r)[0]), "=r"((r)[1]), "=r"((r)[2]), "=r"((r)[3]) : "r"(a))
#define SWZ(b) ((b) ^ ((((uint32_t)(b)) >> 3) & 0x70))

// ---------------- mma.sync split-bf16 GEMM v3 -------------------------------
// D[M][Ncols] = A * B^T over 3 bf16 segments (hi.hi, lo.hi, hi.lo).
// A: [M][lda], row m = hi[0..Kseg) | lo[Kseg..2Kseg). B: [Ncols][ldb] same.
// BK=64 (128B rows), cp.async double buffer, ldmatrix fragments.
// EPI 0: C = D (+bias). EPI 1: C = gelu(D) + resid.
template<int BN, int EPI>
__global__ __launch_bounds__(256)
void mma3(const bf16* __restrict__ A, const bf16* __restrict__ Bm,
          float* __restrict__ C,
          const float* __restrict__ bias, const float* __restrict__ resid,
          int Kseg, long long sA, long long sB, long long sC,
          int lda, int ldb, int ldc)
{
    const int WN  = BN / 2;          // 64 or 32
    const int NTL = WN / 8;          // 8 or 4
    const int ABUF = 128 * 128;      // bytes per A buffer (128 rows x 128B)
    const int BBUF = BN * 128;

    extern __shared__ char dsm[];
    const uint32_t sAs = smem_u32(dsm);
    const uint32_t sBs = sAs + 2 * ABUF;

    const int tid = threadIdx.x, wid = tid >> 5, lane = tid & 31;
    const int wy = wid & 3, wx = wid >> 2;     // 4 x 2 warp grid
    const int bz = blockIdx.z;
    A  += sA * bz;
    Bm += sB * bz;
    C  += sC * bz;
    const float* Rp = (EPI == 1) ? resid + sC * bz : nullptr;
    const int m0 = blockIdx.y * 128;
    const int n0 = blockIdx.x * BN;

    float acc[2][NTL][4];
    #pragma unroll
    for (int i = 0; i < 2; i++)
        #pragma unroll
        for (int j = 0; j < NTL; j++)
            #pragma unroll
            for (int t = 0; t < 4; t++) acc[i][j][t] = 0.0f;

    const int cps = Kseg >> 6;
    const int NC  = 3 * cps;

    auto ldg_async = [&](int c, int buf){
        int seg = c / cps, ck = c - seg * cps;
        long long kA = (long long)((seg == 1) ? Kseg : 0) + ck * 64;
        long long kB = (long long)((seg == 2) ? Kseg : 0) + ck * 64;
        {   // A: 128 rows, 2 threads/row, 4x16B each
            int row = tid >> 1, c0 = (tid & 1) * 4;
            const bf16* gp = &A[(long long)(m0 + row) * lda + kA + c0 * 8];
            uint32_t sp = sAs + buf * ABUF;
            #pragma unroll
            for (int i = 0; i < 4; i++)
                cpa16(sp + SWZ(row * 128 + (c0 + i) * 16), gp + i * 8);
        }
        if (BN == 128){
            int row = tid >> 1, c0 = (tid & 1) * 4;
            const bf16* gp = &Bm[(long long)(n0 + row) * ldb + kB + c0 * 8];
            uint32_t sp = sBs + buf * BBUF;
            #pragma unroll
            for (int i = 0; i < 4; i++)
                cpa16(sp + SWZ(row * 128 + (c0 + i) * 16), gp + i * 8);
        } else {
            int row = tid >> 2, c0 = (tid & 3) * 2;
            const bf16* gp = &Bm[(long long)(n0 + row) * ldb + kB + c0 * 8];
            uint32_t sp = sBs + buf * BBUF;
            #pragma unroll
            for (int i = 0; i < 2; i++)
                cpa16(sp + SWZ(row * 128 + (c0 + i) * 16), gp + i * 8);
        }
    };

    const int g  = lane >> 3;        // ldmatrix address group
    const int li = lane & 7;

    auto compute = [&](int buf){
        const uint32_t aB = sAs + buf * ABUF;
        const uint32_t bB = sBs + buf * BBUF;
        #pragma unroll
        for (int kt = 0; kt < 4; kt++){
            uint32_t af[2][4];
            #pragma unroll
            for (int mt = 0; mt < 2; mt++){
                int row  = wy * 32 + mt * 16 + (g & 1) * 8 + li;
                int kcol = kt * 16 + (g >> 1) * 8;
                LDSM_X4(af[mt], aB + SWZ(row * 128 + kcol * 2));
            }
            uint32_t bfm[NTL][2];
            #pragma unroll
            for (int np = 0; np < NTL / 2; np++){
                int row  = wx * WN + np * 16 + (g >> 1) * 8 + li;
                int kcol = kt * 16 + (g & 1) * 8;
                uint32_t r4[4];
                LDSM_X4(r4, bB + SWZ(row * 128 + kcol * 2));
                bfm[np * 2][0] = r4[0]; bfm[np * 2][1] = r4[1];
                bfm[np * 2 + 1][0] = r4[2]; bfm[np * 2 + 1][1] = r4[3];
            }
            #pragma unroll
            for (int nt = 0; nt < NTL; nt++)
                #pragma unroll
                for (int mt = 0; mt < 2; mt++)
                    asm volatile(
                        "mma.sync.aligned.m16n8k16.row.col.f32.bf16.bf16.f32 "
                        "{%0,%1,%2,%3}, {%4,%5,%6,%7}, {%8,%9}, {%0,%1,%2,%3};"
                        : "+f"(acc[mt][nt][0]), "+f"(acc[mt][nt][1]),
                          "+f"(acc[mt][nt][2]), "+f"(acc[mt][nt][3])
                        : "r"(af[mt][0]), "r"(af[mt][1]), "r"(af[mt][2]), "r"(af[mt][3]),
                          "r"(bfm[nt][0]), "r"(bfm[nt][1]));
        }
    };

    ldg_async(0, 0); CP_COMMIT();
    for (int c = 0; c < NC; c++){
        if (c + 1 < NC){ ldg_async(c + 1, (c + 1) & 1); CP_COMMIT(); CP_WAIT1(); }
        else CP_WAIT0();
        __syncthreads();
        compute(c & 1);
        __syncthreads();
    }

    // ---- epilogue ----
    #pragma unroll
    for (int mt = 0; mt < 2; mt++){
        const int r0 = m0 + wy * 32 + mt * 16 + (lane >> 2);
        const float bv0 = bias ? bias[r0] : 0.0f;
        const float bv8 = bias ? bias[r0 + 8] : 0.0f;
        #pragma unroll
        for (int nt = 0; nt < NTL; nt++){
            const int cIdx = n0 + wx * WN + nt * 8 + (lane & 3) * 2;
            float v0 = acc[mt][nt][0] + bv0, v1 = acc[mt][nt][1] + bv0;
            float v2 = acc[mt][nt][2] + bv8, v3 = acc[mt][nt][3] + bv8;
            const long long o0 = (long long)r0 * ldc + cIdx;
            const long long o8 = (long long)(r0 + 8) * ldc + cIdx;
            if (EPI == 1){
                v0 = 0.5f * v0 * (1.0f + erff(v0 * 0.70710678118654752f)) + Rp[o0];
                v1 = 0.5f * v1 * (1.0f + erff(v1 * 0.70710678118654752f)) + Rp[o0 + 1];
                v2 = 0.5f * v2 * (1.0f + erff(v2 * 0.70710678118654752f)) + Rp[o8];
                v3 = 0.5f * v3 * (1.0f + erff(v3 * 0.70710678118654752f)) + Rp[o8 + 1];
            }
            *reinterpret_cast<float2*>(&C[o0]) = make_float2(v0, v1);
            *reinterpret_cast<float2*>(&C[o8]) = make_float2(v2, v3);
        }
    }
}

// ---------------- elementwise prep kernels ----------------------------------
__global__ void split_w(const float* __restrict__ src, bf16* __restrict__ dst,
                        int K, int total)
{
    int idx = blockIdx.x * blockDim.x + threadIdx.x;
    if (idx >= total) return;
    int mrow = idx / K, k = idx - mrow * K;
    bf16 hi, lo; split2(src[idx], hi, lo);
    long long b = (long long)mrow * 2 * K + k;
    dst[b] = hi;
    dst[b + K] = lo;
}

// split V rows out of stacked qkv: src [b][768][1024] rows 512+p -> dst [b][p][hi|lo]
__global__ void split_v(const float* __restrict__ qkv, bf16* __restrict__ dst)
{
    long long idx = (long long)blockIdx.x * blockDim.x + threadIdx.x;
    if (idx >= 16LL * 256 * 1024) return;
    int k = idx & 1023;
    int p = (int)((idx >> 10) & 255);
    int b = (int)(idx >> 18);
    float v = qkv[((long long)b * 768 + 512 + p) * 1024 + k];
    bf16 hi, lo; split2(v, hi, lo);
    long long o = (((long long)b * 256 + p) * 2048) + k;
    dst[o] = hi;
    dst[o + 1024] = lo;
}

__global__ void pack_bias(const float* __restrict__ bq, const float* __restrict__ bk,
                          const float* __restrict__ bv, float* __restrict__ dst)
{
    int i = blockIdx.x * blockDim.x + threadIdx.x;
    if (i >= 768) return;
    dst[i] = (i < 256) ? bq[i] : (i < 512) ? bk[i - 256] : bv[i - 512];
}

// transpose+split: src [b][C][1024] -> dst [b][n][ldDst] hi @ c, lo @ c+loOff
__global__ void splitT(const float* __restrict__ src, bf16* __restrict__ dst,
                       int Cch, int ldDst, int loOff)
{
    __shared__ float sh[32][33];
    int b = blockIdx.z, n0 = blockIdx.x * 32, c0 = blockIdx.y * 32;
    int tx = threadIdx.x, ty = threadIdx.y;
    sh[ty][tx] = src[((long long)b * Cch + c0 + ty) * N_ + n0 + tx];
    __syncthreads();
    bf16 hi, lo; split2(sh[tx][ty], hi, lo);
    long long base = ((long long)b * N_ + n0 + ty) * ldDst + c0 + tx;
    dst[base] = hi;
    dst[base + loOff] = lo;
}

__global__ void prep_qkT(const float* __restrict__ qkv,
                         const float* __restrict__ rel_h, const float* __restrict__ rel_w,
                         bf16* __restrict__ QpT, bf16* __restrict__ KpT)
{
    __shared__ float sq[32][33], sk[32][33];
    int bh = blockIdx.z, b = bh >> 2, h = bh & 3;
    int n0 = blockIdx.x * 32, dd0 = blockIdx.y * 32;
    int tx = threadIdx.x, ty = threadIdx.y;
    int dd = dd0 + ty, n = n0 + tx;
    float qv, kv;
    if (dd < 64){
        long long src = ((long long)(b * 768 + h * D_ + dd)) * N_ + n;
        qv = qkv[src];
        kv = qkv[src + 256 * 1024];
    } else {
        int d = dd - 64;
        int w = n >> 5, hh = n & 31;
        qv = rel_h[(h * D_ + d) * HH + hh] + rel_w[(h * D_ + d) * WW + w];
        kv = qkv[((long long)(b * 768 + h * D_ + d)) * N_ + n];
    }
    sq[ty][tx] = qv; sk[ty][tx] = kv;
    __syncthreads();
    long long base = ((long long)bh * N_ + n0 + ty) * 256 + dd0 + tx;
    bf16 hi, lo;
    split2(sq[tx][ty], hi, lo); QpT[base] = hi; QpT[base + 128] = lo;
    split2(sk[tx][ty], hi, lo); KpT[base] = hi; KpT[base + 128] = lo;
}

__global__ void softmax_split(const float* __restrict__ S, bf16* __restrict__ P)
{
    int gw = (blockIdx.x * blockDim.x + threadIdx.x) >> 5;
    int lane = threadIdx.x & 31;
    if (gw >= B_ * HEADS * N_) return;
    const float4* row = reinterpret_cast<const float4*>(S + (long long)gw * N_);

    float4 v[8];
    float mx = -1e30f;
    #pragma unroll
    for (int i = 0; i < 8; i++){
        v[i] = row[lane + 32 * i];
        mx = fmaxf(mx, fmaxf(fmaxf(v[i].x, v[i].y), fmaxf(v[i].z, v[i].w)));
    }
    #pragma unroll
    for (int o = 16; o; o >>= 1) mx = fmaxf(mx, __shfl_xor_sync(0xffffffffu, mx, o));
    float sum = 0.f;
    #pragma unroll
    for (int i = 0; i < 8; i++){
        v[i].x = __expf(v[i].x - mx); v[i].y = __expf(v[i].y - mx);
        v[i].z = __expf(v[i].z - mx); v[i].w = __expf(v[i].w - mx);
        sum += v[i].x + v[i].y + v[i].z + v[i].w;
    }
    #pragma unroll
    for (int o = 16; o; o >>= 1) sum += __shfl_xor_sync(0xffffffffu, sum, o);
    float inv = 1.0f / sum;

    __nv_bfloat162* ph = reinterpret_cast<__nv_bfloat162*>(P + (long long)gw * 2048);
    __nv_bfloat162* pl = reinterpret_cast<__nv_bfloat162*>(P + (long long)gw * 2048 + 1024);
    #pragma unroll
    for (int i = 0; i < 8; i++){
        float a = v[i].x * inv, bb = v[i].y * inv, cf = v[i].z * inv, df = v[i].w * inv;
        bf16 ha, hb, hc, hd, la, lb, lc, ld;
        split2(a, ha, la); split2(bb, hb, lb); split2(cf, hc, lc); split2(df, hd, ld);
        int j4 = lane + 32 * i;
        ph[2 * j4]     = __nv_bfloat162(ha, hb);
        ph[2 * j4 + 1] = __nv_bfloat162(hc, hd);
        pl[2 * j4]     = __nv_bfloat162(la, lb);
        pl[2 * j4 + 1] = __nv_bfloat162(lc, ld);
    }
}

__global__ void ln_yT(const float* __restrict__ Ot,
                      const float* __restrict__ ln_w, const float* __restrict__ ln_b,
                      bf16* __restrict__ yT)
{
    __shared__ float s[32][257];
    __shared__ float smu[32], srs[32];
    int b  = blockIdx.y;
    int n0 = blockIdx.x * 32;
    int tid = threadIdx.x;

    for (int idx = tid; idx < 32 * 256; idx += 256){
        int p  = idx & 255;
        int ni = idx >> 8;
        int h = p >> 6, d = p & 63;
        s[ni][p] = Ot[(((long long)(b * HEADS + h)) * N_ + n0 + ni) * D_ + d];
    }
    __syncthreads();

    int warp = tid >> 5, lane = tid & 31;
    for (int r = warp; r < 32; r += 8){
        float sum = 0.f, sq = 0.f;
        for (int c = lane; c < 256; c += 32){
            float xv = s[r][c];
            sum += xv; sq += xv * xv;
        }
        #pragma unroll
        for (int o = 16; o; o >>= 1){
            sum += __shfl_xor_sync(0xffffffffu, sum, o);
            sq  += __shfl_xor_sync(0xffffffffu, sq, o);
        }
        if (lane == 0){
            float mu = sum * (1.0f / 256.0f);
            float var = sq * (1.0f / 256.0f) - mu * mu;
            smu[r] = mu;
            srs[r] = rsqrtf(var + 1e-6f);
        }
    }
    __syncthreads();

    for (int idx = tid; idx < 32 * 256; idx += 256){
        int p  = idx & 255;
        int ni = idx >> 8;
        float val = (s[ni][p] - smu[ni]) * srs[ni] * ln_w[p] + ln_b[p];
        bf16 hi, lo; split2(val, hi, lo);
        long long base = ((long long)b * N_ + n0 + ni) * 512 + p;
        yT[base] = hi;
        yT[base + 256] = lo;
    }
}

// ---------------- launch -------------------------------------------------------
extern "C" void kernel_launch(void* const* d_in, const int* in_sizes, int n_in,
                              void* d_out, int out_size)
{
    const float* x     = (const float*)d_in[0];
    const float* w_ds  = (const float*)d_in[1];
    const float* wq    = (const float*)d_in[2];
    const float* bq    = (const float*)d_in[3];
    const float* wk    = (const float*)d_in[4];
    const float* bk    = (const float*)d_in[5];
    const float* wv    = (const float*)d_in[6];
    const float* bv    = (const float*)d_in[7];
    const float* rel_h = (const float*)d_in[8];
    const float* rel_w = (const float*)d_in[9];
    const float* ln_w  = (const float*)d_in[10];
    const float* ln_b  = (const float*)d_in[11];
    const float* w1    = (const float*)d_in[12];
    float* out = (float*)d_out;

    bf16 *pWds, *pWqkv, *pW1, *pXT, *pBufT, *pV2, *pQpT, *pKpT, *pP, *pYT;
    float *pBuf, *pQKV, *pBq, *pS, *pOt;
    cudaGetSymbolAddress((void**)&pWds,  g_wds2);
    cudaGetSymbolAddress((void**)&pWqkv, g_wqkv2);
    cudaGetSymbolAddress((void**)&pBq,   g_bqkv);
    cudaGetSymbolAddress((void**)&pW1,   g_w12);
    cudaGetSymbolAddress((void**)&pXT,   g_xT);
    cudaGetSymbolAddress((void**)&pBuf,  g_buf);
    cudaGetSymbolAddress((void**)&pBufT, g_bufT);
    cudaGetSymbolAddress((void**)&pQKV,  g_qkv);
    cudaGetSymbolAddress((void**)&pV2,   g_V2);
    cudaGetSymbolAddress((void**)&pQpT,  g_QpT);
    cudaGetSymbolAddress((void**)&pKpT,  g_KpT);
    cudaGetSymbolAddress((void**)&pS,    g_S);
    cudaGetSymbolAddress((void**)&pP,    g_P);
    cudaGetSymbolAddress((void**)&pOt,   g_Ot);
    cudaGetSymbolAddress((void**)&pYT,   g_yT);

    const int SM128 = 2 * 128 * 128 + 2 * 128 * 128;   // 65536
    const int SM64  = 2 * 128 * 128 + 2 * 64 * 128;    // 49152
    static int attr_done = 0;
    if (!attr_done){
        cudaFuncSetAttribute(mma3<128,0>, cudaFuncAttributeMaxDynamicSharedMemorySize, SM128);
        cudaFuncSetAttribute(mma3<128,1>, cudaFuncAttributeMaxDynamicSharedMemorySize, SM128);
        cudaFuncSetAttribute(mma3<64,0>,  cudaFuncAttributeMaxDynamicSharedMemorySize, SM64);
        attr_done = 1;
    }

    // 0) weight/input prep
    split_w<<<(256*1024 + 255)/256, 256>>>(w_ds, pWds, 1024, 256*1024);
    split_w<<<(256*256  + 255)/256, 256>>>(wq, pWqkv,            256, 256*256);
    split_w<<<(256*256  + 255)/256, 256>>>(wk, pWqkv + 256*512,  256, 256*256);
    split_w<<<(256*256  + 255)/256, 256>>>(wv, pWqkv + 512*512,  256, 256*256);
    split_w<<<(1024*256 + 255)/256, 256>>>(w1, pW1, 256, 1024*256);
    pack_bias<<<3, 256>>>(bq, bk, bv, pBq);
    splitT<<<dim3(32, 32, B_), dim3(32, 32)>>>(x, pXT, 1024, 2048, 1024);

    // 1) downsample: buf = w_ds @ x  (M=256, N=1024, Kseg=1024)
    mma3<128,0><<<dim3(8, 2, B_), 256, SM128>>>(pWds, pXT, pBuf, nullptr, nullptr,
        1024, 0, 1024LL*2048, 256LL*1024, 2048, 2048, 1024);
    splitT<<<dim3(32, 8, B_), dim3(32, 32)>>>(pBuf, pBufT, 256, 512, 256);

    // 2) fused QKV projection (M=768, N=1024, Kseg=256)
    mma3<128,0><<<dim3(8, 6, B_), 256, SM128>>>(pWqkv, pBufT, pQKV, pBq, nullptr,
        256, 0, 1024LL*512, 768LL*1024, 512, 512, 1024);
    split_v<<<(int)((16LL*256*1024 + 255)/256), 256>>>(pQKV, pV2);

    // 3) Qp^T / Kp^T (split, n-major)
    prep_qkT<<<dim3(32, 4, B_*HEADS), dim3(32, 32)>>>(pQKV, rel_h, rel_w, pQpT, pKpT);

    // 4) logits S = Qp^T . Kp  (M=1024, N=1024, Kseg=128, batch 64)
    mma3<128,0><<<dim3(8, 8, B_*HEADS), 256, SM128>>>(pQpT, pKpT, pS, nullptr, nullptr,
        128, 1024LL*256, 1024LL*256, 1024LL*1024, 256, 256, 1024);

    // 5) softmax -> split probs
    softmax_split<<<(B_*HEADS*N_) / 8, 256>>>(pS, pP);

    // 6) Ot = P . V^T  (M=1024, N=64, Kseg=1024, batch 64)
    mma3<64,0><<<dim3(1, 8, B_*HEADS), 256, SM64>>>(pP, pV2, pOt, nullptr, nullptr,
        1024, 1024LL*2048, 64LL*2048, 1024LL*64, 2048, 2048, 64);

    // 7) LayerNorm -> y^T split
    ln_yT<<<dim3(32, B_), 256>>>(pOt, ln_w, ln_b, pYT);

    // 8) expand + exact GELU + residual (M=1024, N=1024, Kseg=256)
    mma3<128,1><<<dim3(8, 8, B_), 256, SM128>>>(pW1, pYT, out, nullptr, x,
        256, 0, 1024LL*512, 1024LL*1024, 512, 512, 1024);
}

// round 12
// speedup vs baseline: 2.5678x; 1.2140x over previous
#include <cuda_runtime.h>
#include <cuda_bf16.h>
#include <math.h>
#include <stdint.h>

#define B_    16
#define INC   1024
#define P_    256
#define HEADS 4
#define D_    64
#define N_    1024
#define WW    32
#define HH    32

typedef __nv_bfloat16 bf16;

// ---------------- scratch (static device globals) ---------------------------
__device__ bf16  g_wds2 [256*2048];
__device__ bf16  g_wqkv2[768*512];
__device__ float g_bqkv [768];
__device__ bf16  g_w12  [1024*512];
__device__ bf16  g_xT   [16LL*1024*2048];   // [b][n][hi c|lo c]
__device__ float g_buf  [16*256*1024];      // downsample out fp32 [b][p][n]
__device__ bf16  g_bufT [16LL*1024*512];    // [b][n][hi p|lo p]
__device__ float g_qkv  [16LL*768*1024];    // q 0-255, k 256-511, v 512-767
__device__ bf16  g_V2   [16LL*256*2048];    // [b][p][hi j|lo j]
__device__ bf16  g_QpT  [64LL*1024*256];    // [bh][n][hi dd|lo dd]
__device__ bf16  g_KpT  [64LL*1024*256];
__device__ float g_Ot   [64LL*1024*64];
__device__ bf16  g_yT   [16LL*1024*512];    // [b][n][hi p|lo p]

__device__ __forceinline__ void split2(float v, bf16& hi, bf16& lo){
    hi = __float2bfloat16(v);
    lo = __float2bfloat16(v - __bfloat162float(hi));
}
__device__ __forceinline__ uint32_t smem_u32(const void* p){
    uint32_t a;
    asm("{ .reg .u64 t; cvta.to.shared.u64 t, %1; cvt.u32.u64 %0, t; }" : "=r"(a) : "l"(p));
    return a;
}
__device__ __forceinline__ void cpa16(uint32_t s, const void* g){
    asm volatile("cp.async.cg.shared.global [%0], [%1], 16;" :: "r"(s), "l"(g));
}
#define CP_COMMIT() asm volatile("cp.async.commit_group;" ::: "memory")
#define CP_WAIT1()  asm volatile("cp.async.wait_group 1;" ::: "memory")
#define CP_WAIT0()  asm volatile("cp.async.wait_group 0;" ::: "memory")
#define LDSM_X4(r, a) \
    asm volatile("ldmatrix.sync.aligned.m8n8.x4.shared.b16 {%0,%1,%2,%3}, [%4];" \
        : "=r"((r)[0]), "=r"((r)[1]), "=r"((r)[2]), "=r"((r)[3]) : "r"(a))
#define SWZ(b) ((b) ^ ((((uint32_t)(b)) >> 3) & 0x70))

__device__ __forceinline__ void mma16816(float* c, const uint32_t* a, const uint32_t* b){
    asm volatile("mma.sync.aligned.m16n8k16.row.col.f32.bf16.bf16.f32 "
        "{%0,%1,%2,%3}, {%4,%5,%6,%7}, {%8,%9}, {%0,%1,%2,%3};"
        : "+f"(c[0]), "+f"(c[1]), "+f"(c[2]), "+f"(c[3])
        : "r"(a[0]), "r"(a[1]), "r"(a[2]), "r"(a[3]), "r"(b[0]), "r"(b[1]));
}
__device__ __forceinline__ uint32_t pack_bf2(float x, float y){
    __nv_bfloat162 t = __floats2bfloat162_rn(x, y);
    return *reinterpret_cast<uint32_t*>(&t);
}

// ---------------- mma.sync split-bf16 GEMM (R11, unchanged) ------------------
template<int BN, int EPI>
__global__ __launch_bounds__(256)
void mma3(const bf16* __restrict__ A, const bf16* __restrict__ Bm,
          float* __restrict__ C,
          const float* __restrict__ bias, const float* __restrict__ resid,
          int Kseg, long long sA, long long sB, long long sC,
          int lda, int ldb, int ldc)
{
    const int WN  = BN / 2;
    const int NTL = WN / 8;
    const int ABUF = 128 * 128;
    const int BBUF = BN * 128;

    extern __shared__ char dsm[];
    const uint32_t sAs = smem_u32(dsm);
    const uint32_t sBs = sAs + 2 * ABUF;

    const int tid = threadIdx.x, wid = tid >> 5, lane = tid & 31;
    const int wy = wid & 3, wx = wid >> 2;
    const int bz = blockIdx.z;
    A  += sA * bz;
    Bm += sB * bz;
    C  += sC * bz;
    const float* Rp = (EPI == 1) ? resid + sC * bz : nullptr;
    const int m0 = blockIdx.y * 128;
    const int n0 = blockIdx.x * BN;

    float acc[2][NTL][4];
    #pragma unroll
    for (int i = 0; i < 2; i++)
        #pragma unroll
        for (int j = 0; j < NTL; j++)
            #pragma unroll
            for (int t = 0; t < 4; t++) acc[i][j][t] = 0.0f;

    const int cps = Kseg >> 6;
    const int NC  = 3 * cps;

    auto ldg_async = [&](int c, int buf){
        int seg = c / cps, ck = c - seg * cps;
        long long kA = (long long)((seg == 1) ? Kseg : 0) + ck * 64;
        long long kB = (long long)((seg == 2) ? Kseg : 0) + ck * 64;
        {
            int row = tid >> 1, c0 = (tid & 1) * 4;
            const bf16* gp = &A[(long long)(m0 + row) * lda + kA + c0 * 8];
            uint32_t sp = sAs + buf * ABUF;
            #pragma unroll
            for (int i = 0; i < 4; i++)
                cpa16(sp + SWZ(row * 128 + (c0 + i) * 16), gp + i * 8);
        }
        if (BN == 128){
            int row = tid >> 1, c0 = (tid & 1) * 4;
            const bf16* gp = &Bm[(long long)(n0 + row) * ldb + kB + c0 * 8];
            uint32_t sp = sBs + buf * BBUF;
            #pragma unroll
            for (int i = 0; i < 4; i++)
                cpa16(sp + SWZ(row * 128 + (c0 + i) * 16), gp + i * 8);
        } else {
            int row = tid >> 2, c0 = (tid & 3) * 2;
            const bf16* gp = &Bm[(long long)(n0 + row) * ldb + kB + c0 * 8];
            uint32_t sp = sBs + buf * BBUF;
            #pragma unroll
            for (int i = 0; i < 2; i++)
                cpa16(sp + SWZ(row * 128 + (c0 + i) * 16), gp + i * 8);
        }
    };

    const int g  = lane >> 3;
    const int li = lane & 7;

    auto compute = [&](int buf){
        const uint32_t aB = sAs + buf * ABUF;
        const uint32_t bB = sBs + buf * BBUF;
        #pragma unroll
        for (int kt = 0; kt < 4; kt++){
            uint32_t af[2][4];
            #pragma unroll
            for (int mt = 0; mt < 2; mt++){
                int row  = wy * 32 + mt * 16 + (g & 1) * 8 + li;
                int kcol = kt * 16 + (g >> 1) * 8;
                LDSM_X4(af[mt], aB + SWZ(row * 128 + kcol * 2));
            }
            uint32_t bfm[NTL][2];
            #pragma unroll
            for (int np = 0; np < NTL / 2; np++){
                int row  = wx * WN + np * 16 + (g >> 1) * 8 + li;
                int kcol = kt * 16 + (g & 1) * 8;
                uint32_t r4[4];
                LDSM_X4(r4, bB + SWZ(row * 128 + kcol * 2));
                bfm[np * 2][0] = r4[0]; bfm[np * 2][1] = r4[1];
                bfm[np * 2 + 1][0] = r4[2]; bfm[np * 2 + 1][1] = r4[3];
            }
            #pragma unroll
            for (int nt = 0; nt < NTL; nt++)
                #pragma unroll
                for (int mt = 0; mt < 2; mt++)
                    mma16816(acc[mt][nt], af[mt], bfm[nt]);
        }
    };

    ldg_async(0, 0); CP_COMMIT();
    for (int c = 0; c < NC; c++){
        if (c + 1 < NC){ ldg_async(c + 1, (c + 1) & 1); CP_COMMIT(); CP_WAIT1(); }
        else CP_WAIT0();
        __syncthreads();
        compute(c & 1);
        __syncthreads();
    }

    #pragma unroll
    for (int mt = 0; mt < 2; mt++){
        const int r0 = m0 + wy * 32 + mt * 16 + (lane >> 2);
        const float bv0 = bias ? bias[r0] : 0.0f;
        const float bv8 = bias ? bias[r0 + 8] : 0.0f;
        #pragma unroll
        for (int nt = 0; nt < NTL; nt++){
            const int cIdx = n0 + wx * WN + nt * 8 + (lane & 3) * 2;
            float v0 = acc[mt][nt][0] + bv0, v1 = acc[mt][nt][1] + bv0;
            float v2 = acc[mt][nt][2] + bv8, v3 = acc[mt][nt][3] + bv8;
            const long long o0 = (long long)r0 * ldc + cIdx;
            const long long o8 = (long long)(r0 + 8) * ldc + cIdx;
            if (EPI == 1){
                v0 = 0.5f * v0 * (1.0f + erff(v0 * 0.70710678118654752f)) + Rp[o0];
                v1 = 0.5f * v1 * (1.0f + erff(v1 * 0.70710678118654752f)) + Rp[o0 + 1];
                v2 = 0.5f * v2 * (1.0f + erff(v2 * 0.70710678118654752f)) + Rp[o8];
                v3 = 0.5f * v3 * (1.0f + erff(v3 * 0.70710678118654752f)) + Rp[o8 + 1];
            }
            *reinterpret_cast<float2*>(&C[o0]) = make_float2(v0, v1);
            *reinterpret_cast<float2*>(&C[o8]) = make_float2(v2, v3);
        }
    }
}

// ---------------- fused flash attention --------------------------------------
// grid (8 i-tiles, 64 bh), 256 threads. Qp tile resident; K/V j-tiles (64 wide)
// double-buffered. Each warp owns 16 m-rows x full 64 n.
__global__ __launch_bounds__(256)
void flash_attn(const bf16* __restrict__ QpT, const bf16* __restrict__ KpT,
                const bf16* __restrict__ V2, float* __restrict__ Ot)
{
    extern __shared__ char sm[];
    const uint32_t sA = smem_u32(sm);            // 4 chunks x 16KB = 64KB
    const uint32_t sK = sA + 65536;              // 2 bufs x 4 chunks x 8KB = 64KB
    const uint32_t sV = sK + 65536;              // 2 bufs x 2 segs x 8KB = 32KB

    const int bh = blockIdx.y;
    const int b = bh >> 2, h = bh & 3;
    const int i0 = blockIdx.x * 128;
    const bf16* Qb = QpT + (long long)bh * 1024 * 256;
    const bf16* Kb = KpT + (long long)bh * 1024 * 256;
    const bf16* Vb = V2 + ((long long)b * 256 + h * 64) * 2048;

    const int tid = threadIdx.x, wid = tid >> 5, lane = tid & 31;
    const int g = lane >> 3, li = lane & 7;
    const int r = lane >> 2, q = lane & 3;

    // resident A (Qp i-tile): 128 rows x 256 bf16 -> 4 chunks of 64 cols
    {
        int row = tid >> 1, c4 = (tid & 1) * 4;
        #pragma unroll
        for (int ch = 0; ch < 4; ch++){
            const bf16* gp = Qb + (long long)(i0 + row) * 256 + ch * 64 + c4 * 8;
            #pragma unroll
            for (int i = 0; i < 4; i++)
                cpa16(sA + ch * 16384 + SWZ(row * 128 + (c4 + i) * 16), gp + i * 8);
        }
    }
    auto ldKV = [&](int jt, int buf){
        int row = tid >> 2, c16 = tid & 3;
        #pragma unroll
        for (int ch = 0; ch < 4; ch++){
            const bf16* gp = Kb + (long long)(jt * 64 + row) * 256 + ch * 64;
            uint32_t base = sK + buf * 32768 + ch * 8192;
            cpa16(base + SWZ(row * 128 + c16 * 16), gp + c16 * 8);
            cpa16(base + SWZ(row * 128 + (c16 + 4) * 16), gp + (c16 + 4) * 8);
        }
        const bf16* gv = Vb + (long long)row * 2048 + jt * 64;
        uint32_t vb0 = sV + buf * 16384;
        cpa16(vb0 + SWZ(row * 128 + c16 * 16), gv + c16 * 8);
        cpa16(vb0 + SWZ(row * 128 + (c16 + 4) * 16), gv + (c16 + 4) * 8);
        const bf16* gv2 = gv + 1024;
        cpa16(vb0 + 8192 + SWZ(row * 128 + c16 * 16), gv2 + c16 * 8);
        cpa16(vb0 + 8192 + SWZ(row * 128 + (c16 + 4) * 16), gv2 + (c16 + 4) * 8);
    };

    ldKV(0, 0); CP_COMMIT();

    float m0v = -1e30f, m1v = -1e30f, l0 = 0.f, l1 = 0.f;
    float O[8][4];
    #pragma unroll
    for (int i = 0; i < 8; i++)
        #pragma unroll
        for (int t = 0; t < 4; t++) O[i][t] = 0.f;

    for (int jt = 0; jt < 16; jt++){
        CP_WAIT0();
        __syncthreads();
        if (jt + 1 < 16){ ldKV(jt + 1, (jt + 1) & 1); CP_COMMIT(); }

        // ---- S = Qp_i . Kp_j^T (3 segments) ----
        float S[8][4];
        #pragma unroll
        for (int i = 0; i < 8; i++)
            #pragma unroll
            for (int t = 0; t < 4; t++) S[i][t] = 0.f;

        const uint32_t kB = sK + (jt & 1) * 32768;
        #pragma unroll
        for (int seg = 0; seg < 3; seg++){
            const int aoff = (seg == 1) ? 2 : 0;
            const int koff = (seg == 2) ? 2 : 0;
            #pragma unroll
            for (int kc = 0; kc < 2; kc++){
                const uint32_t aCh = sA + (aoff + kc) * 16384;
                const uint32_t kCh = kB + (koff + kc) * 8192;
                #pragma unroll
                for (int kt = 0; kt < 4; kt++){
                    uint32_t af[4];
                    LDSM_X4(af, aCh + SWZ((wid * 16 + (g & 1) * 8 + li) * 128
                                          + (kt * 16 + (g >> 1) * 8) * 2));
                    uint32_t bfm[8][2];
                    #pragma unroll
                    for (int np = 0; np < 4; np++){
                        uint32_t r4[4];
                        LDSM_X4(r4, kCh + SWZ((np * 16 + (g >> 1) * 8 + li) * 128
                                              + (kt * 16 + (g & 1) * 8) * 2));
                        bfm[np * 2][0] = r4[0]; bfm[np * 2][1] = r4[1];
                        bfm[np * 2 + 1][0] = r4[2]; bfm[np * 2 + 1][1] = r4[3];
                    }
                    #pragma unroll
                    for (int nt = 0; nt < 8; nt++)
                        mma16816(S[nt], af, bfm[nt]);
                }
            }
        }

        // ---- online softmax (rows r and r+8 of this warp) ----
        float mx0 = -1e30f, mx1 = -1e30f;
        #pragma unroll
        for (int nt = 0; nt < 8; nt++){
            mx0 = fmaxf(mx0, fmaxf(S[nt][0], S[nt][1]));
            mx1 = fmaxf(mx1, fmaxf(S[nt][2], S[nt][3]));
        }
        mx0 = fmaxf(mx0, __shfl_xor_sync(0xffffffffu, mx0, 1));
        mx0 = fmaxf(mx0, __shfl_xor_sync(0xffffffffu, mx0, 2));
        mx1 = fmaxf(mx1, __shfl_xor_sync(0xffffffffu, mx1, 1));
        mx1 = fmaxf(mx1, __shfl_xor_sync(0xffffffffu, mx1, 2));
        const float mn0 = fmaxf(m0v, mx0), mn1 = fmaxf(m1v, mx1);
        const float a0 = __expf(m0v - mn0), a1 = __expf(m1v - mn1);
        m0v = mn0; m1v = mn1;

        float rs0 = 0.f, rs1 = 0.f;
        #pragma unroll
        for (int nt = 0; nt < 8; nt++){
            S[nt][0] = __expf(S[nt][0] - mn0);
            S[nt][1] = __expf(S[nt][1] - mn0);
            S[nt][2] = __expf(S[nt][2] - mn1);
            S[nt][3] = __expf(S[nt][3] - mn1);
            rs0 += S[nt][0] + S[nt][1];
            rs1 += S[nt][2] + S[nt][3];
        }
        rs0 += __shfl_xor_sync(0xffffffffu, rs0, 1);
        rs0 += __shfl_xor_sync(0xffffffffu, rs0, 2);
        rs1 += __shfl_xor_sync(0xffffffffu, rs1, 1);
        rs1 += __shfl_xor_sync(0xffffffffu, rs1, 2);
        l0 = l0 * a0 + rs0;
        l1 = l1 * a1 + rs1;
        #pragma unroll
        for (int dt = 0; dt < 8; dt++){
            O[dt][0] *= a0; O[dt][1] *= a0;
            O[dt][2] *= a1; O[dt][3] *= a1;
        }

        // ---- O += P . V (3 terms: Phi.Vhi + Plo.Vhi + Phi.Vlo) ----
        const uint32_t vB = sV + (jt & 1) * 16384;
        #pragma unroll
        for (int kt = 0; kt < 4; kt++){
            // A fragments from S registers (C layout == A layout)
            uint32_t ah[4], al[4];
            #pragma unroll
            for (int hvv = 0; hvv < 2; hvv++){
                const float* p = S[kt * 2 + hvv];
                bf16 h0, l0b, h1, l1b, h2, l2b, h3, l3b;
                split2(p[0], h0, l0b); split2(p[1], h1, l1b);
                split2(p[2], h2, l2b); split2(p[3], h3, l3b);
                __nv_bfloat162 ph0(h0, h1), ph1(h2, h3), pl0(l0b, l1b), pl1(l2b, l3b);
                ah[hvv * 2 + 0 ? 2 * hvv : 0] = 0; // placeholder (overwritten below)
                ah[2 * hvv]     = *reinterpret_cast<uint32_t*>(&ph0);
                ah[2 * hvv + 1] = *reinterpret_cast<uint32_t*>(&ph1);
                al[2 * hvv]     = *reinterpret_cast<uint32_t*>(&pl0);
                al[2 * hvv + 1] = *reinterpret_cast<uint32_t*>(&pl1);
            }
            uint32_t bh_[8][2], bl_[8][2];
            #pragma unroll
            for (int np = 0; np < 4; np++){
                uint32_t r4[4];
                LDSM_X4(r4, vB + SWZ((np * 16 + (g >> 1) * 8 + li) * 128
                                     + (kt * 16 + (g & 1) * 8) * 2));
                bh_[np * 2][0] = r4[0]; bh_[np * 2][1] = r4[1];
                bh_[np * 2 + 1][0] = r4[2]; bh_[np * 2 + 1][1] = r4[3];
                LDSM_X4(r4, vB + 8192 + SWZ((np * 16 + (g >> 1) * 8 + li) * 128
                                            + (kt * 16 + (g & 1) * 8) * 2));
                bl_[np * 2][0] = r4[0]; bl_[np * 2][1] = r4[1];
                bl_[np * 2 + 1][0] = r4[2]; bl_[np * 2 + 1][1] = r4[3];
            }
            #pragma unroll
            for (int dt = 0; dt < 8; dt++){
                mma16816(O[dt], ah, bh_[dt]);
                mma16816(O[dt], al, bh_[dt]);
                mma16816(O[dt], ah, bl_[dt]);
            }
        }
    }

    // ---- epilogue: O / l -> Ot[bh][i][64] ----
    const float inv0 = 1.0f / l0, inv1 = 1.0f / l1;
    const int row0 = i0 + wid * 16 + r;
    float* o0p = Ot + ((long long)bh * 1024 + row0) * 64;
    float* o8p = o0p + 8 * 64;
    #pragma unroll
    for (int dt = 0; dt < 8; dt++){
        *reinterpret_cast<float2*>(o0p + dt * 8 + q * 2) =
            make_float2(O[dt][0] * inv0, O[dt][1] * inv0);
        *reinterpret_cast<float2*>(o8p + dt * 8 + q * 2) =
            make_float2(O[dt][2] * inv1, O[dt][3] * inv1);
    }
}

// ---------------- elementwise prep kernels ----------------------------------
__global__ void split_w(const float* __restrict__ src, bf16* __restrict__ dst,
                        int K, int total)
{
    int idx = blockIdx.x * blockDim.x + threadIdx.x;
    if (idx >= total) return;
    int mrow = idx / K, k = idx - mrow * K;
    bf16 hi, lo; split2(src[idx], hi, lo);
    long long b = (long long)mrow * 2 * K + k;
    dst[b] = hi;
    dst[b + K] = lo;
}

__global__ void split_v(const float* __restrict__ qkv, bf16* __restrict__ dst)
{
    long long idx = (long long)blockIdx.x * blockDim.x + threadIdx.x;
    if (idx >= 16LL * 256 * 1024) return;
    int k = idx & 1023;
    int p = (int)((idx >> 10) & 255);
    int b = (int)(idx >> 18);
    float v = qkv[((long long)b * 768 + 512 + p) * 1024 + k];
    bf16 hi, lo; split2(v, hi, lo);
    long long o = (((long long)b * 256 + p) * 2048) + k;
    dst[o] = hi;
    dst[o + 1024] = lo;
}

__global__ void pack_bias(const float* __restrict__ bq, const float* __restrict__ bk,
                          const float* __restrict__ bv, float* __restrict__ dst)
{
    int i = blockIdx.x * blockDim.x + threadIdx.x;
    if (i >= 768) return;
    dst[i] = (i < 256) ? bq[i] : (i < 512) ? bk[i - 256] : bv[i - 512];
}

__global__ void splitT(const float* __restrict__ src, bf16* __restrict__ dst,
                       int Cch, int ldDst, int loOff)
{
    __shared__ float sh[32][33];
    int b = blockIdx.z, n0 = blockIdx.x * 32, c0 = blockIdx.y * 32;
    int tx = threadIdx.x, ty = threadIdx.y;
    sh[ty][tx] = src[((long long)b * Cch + c0 + ty) * N_ + n0 + tx];
    __syncthreads();
    bf16 hi, lo; split2(sh[tx][ty], hi, lo);
    long long base = ((long long)b * N_ + n0 + ty) * ldDst + c0 + tx;
    dst[base] = hi;
    dst[base + loOff] = lo;
}

__global__ void prep_qkT(const float* __restrict__ qkv,
                         const float* __restrict__ rel_h, const float* __restrict__ rel_w,
                         bf16* __restrict__ QpT, bf16* __restrict__ KpT)
{
    __shared__ float sq[32][33], sk[32][33];
    int bh = blockIdx.z, b = bh >> 2, h = bh & 3;
    int n0 = blockIdx.x * 32, dd0 = blockIdx.y * 32;
    int tx = threadIdx.x, ty = threadIdx.y;
    int dd = dd0 + ty, n = n0 + tx;
    float qv, kv;
    if (dd < 64){
        long long src = ((long long)(b * 768 + h * D_ + dd)) * N_ + n;
        qv = qkv[src];
        kv = qkv[src + 256 * 1024];
    } else {
        int d = dd - 64;
        int w = n >> 5, hh = n & 31;
        qv = rel_h[(h * D_ + d) * HH + hh] + rel_w[(h * D_ + d) * WW + w];
        kv = qkv[((long long)(b * 768 + h * D_ + d)) * N_ + n];
    }
    sq[ty][tx] = qv; sk[ty][tx] = kv;
    __syncthreads();
    long long base = ((long long)bh * N_ + n0 + ty) * 256 + dd0 + tx;
    bf16 hi, lo;
    split2(sq[tx][ty], hi, lo); QpT[base] = hi; QpT[base + 128] = lo;
    split2(sk[tx][ty], hi, lo); KpT[base] = hi; KpT[base + 128] = lo;
}

__global__ void ln_yT(const float* __restrict__ Ot,
                      const float* __restrict__ ln_w, const float* __restrict__ ln_b,
                      bf16* __restrict__ yT)
{
    __shared__ float s[32][257];
    __shared__ float smu[32], srs[32];
    int b  = blockIdx.y;
    int n0 = blockIdx.x * 32;
    int tid = threadIdx.x;

    for (int idx = tid; idx < 32 * 256; idx += 256){
        int p  = idx & 255;
        int ni = idx >> 8;
        int h = p >> 6, d = p & 63;
        s[ni][p] = Ot[(((long long)(b * HEADS + h)) * N_ + n0 + ni) * D_ + d];
    }
    __syncthreads();

    int warp = tid >> 5, lane = tid & 31;
    for (int r = warp; r < 32; r += 8){
        float sum = 0.f, sq = 0.f;
        for (int c = lane; c < 256; c += 32){
            float xv = s[r][c];
            sum += xv; sq += xv * xv;
        }
        #pragma unroll
        for (int o = 16; o; o >>= 1){
            sum += __shfl_xor_sync(0xffffffffu, sum, o);
            sq  += __shfl_xor_sync(0xffffffffu, sq, o);
        }
        if (lane == 0){
            float mu = sum * (1.0f / 256.0f);
            float var = sq * (1.0f / 256.0f) - mu * mu;
            smu[r] = mu;
            srs[r] = rsqrtf(var + 1e-6f);
        }
    }
    __syncthreads();

    for (int idx = tid; idx < 32 * 256; idx += 256){
        int p  = idx & 255;
        int ni = idx >> 8;
        float val = (s[ni][p] - smu[ni]) * srs[ni] * ln_w[p] + ln_b[p];
        bf16 hi, lo; split2(val, hi, lo);
        long long base = ((long long)b * N_ + n0 + ni) * 512 + p;
        yT[base] = hi;
        yT[base + 256] = lo;
    }
}

// ---------------- launch -------------------------------------------------------
extern "C" void kernel_launch(void* const* d_in, const int* in_sizes, int n_in,
                              void* d_out, int out_size)
{
    const float* x     = (const float*)d_in[0];
    const float* w_ds  = (const float*)d_in[1];
    const float* wq    = (const float*)d_in[2];
    const float* bq    = (const float*)d_in[3];
    const float* wk    = (const float*)d_in[4];
    const float* bk    = (const float*)d_in[5];
    const float* wv    = (const float*)d_in[6];
    const float* bv    = (const float*)d_in[7];
    const float* rel_h = (const float*)d_in[8];
    const float* rel_w = (const float*)d_in[9];
    const float* ln_w  = (const float*)d_in[10];
    const float* ln_b  = (const float*)d_in[11];
    const float* w1    = (const float*)d_in[12];
    float* out = (float*)d_out;

    bf16 *pWds, *pWqkv, *pW1, *pXT, *pBufT, *pV2, *pQpT, *pKpT, *pYT;
    float *pBuf, *pQKV, *pBq, *pOt;
    cudaGetSymbolAddress((void**)&pWds,  g_wds2);
    cudaGetSymbolAddress((void**)&pWqkv, g_wqkv2);
    cudaGetSymbolAddress((void**)&pBq,   g_bqkv);
    cudaGetSymbolAddress((void**)&pW1,   g_w12);
    cudaGetSymbolAddress((void**)&pXT,   g_xT);
    cudaGetSymbolAddress((void**)&pBuf,  g_buf);
    cudaGetSymbolAddress((void**)&pBufT, g_bufT);
    cudaGetSymbolAddress((void**)&pQKV,  g_qkv);
    cudaGetSymbolAddress((void**)&pV2,   g_V2);
    cudaGetSymbolAddress((void**)&pQpT,  g_QpT);
    cudaGetSymbolAddress((void**)&pKpT,  g_KpT);
    cudaGetSymbolAddress((void**)&pOt,   g_Ot);
    cudaGetSymbolAddress((void**)&pYT,   g_yT);

    const int SM128 = 2 * 128 * 128 + 2 * 128 * 128;   // 65536
    const int SMFA  = 65536 + 65536 + 32768;           // 163840
    static int attr_done = 0;
    if (!attr_done){
        cudaFuncSetAttribute(mma3<128,0>, cudaFuncAttributeMaxDynamicSharedMemorySize, SM128);
        cudaFuncSetAttribute(mma3<128,1>, cudaFuncAttributeMaxDynamicSharedMemorySize, SM128);
        cudaFuncSetAttribute(flash_attn,  cudaFuncAttributeMaxDynamicSharedMemorySize, SMFA);
        attr_done = 1;
    }

    // 0) weight/input prep
    split_w<<<(256*1024 + 255)/256, 256>>>(w_ds, pWds, 1024, 256*1024);
    split_w<<<(256*256  + 255)/256, 256>>>(wq, pWqkv,            256, 256*256);
    split_w<<<(256*256  + 255)/256, 256>>>(wk, pWqkv + 256*512,  256, 256*256);
    split_w<<<(256*256  + 255)/256, 256>>>(wv, pWqkv + 512*512,  256, 256*256);
    split_w<<<(1024*256 + 255)/256, 256>>>(w1, pW1, 256, 1024*256);
    pack_bias<<<3, 256>>>(bq, bk, bv, pBq);
    splitT<<<dim3(32, 32, B_), dim3(32, 32)>>>(x, pXT, 1024, 2048, 1024);

    // 1) downsample: buf = w_ds @ x  (M=256, N=1024, Kseg=1024)
    mma3<128,0><<<dim3(8, 2, B_), 256, SM128>>>(pWds, pXT, pBuf, nullptr, nullptr,
        1024, 0, 1024LL*2048, 256LL*1024, 2048, 2048, 1024);
    splitT<<<dim3(32, 8, B_), dim3(32, 32)>>>(pBuf, pBufT, 256, 512, 256);

    // 2) fused QKV projection (M=768, N=1024, Kseg=256)
    mma3<128,0><<<dim3(8, 6, B_), 256, SM128>>>(pWqkv, pBufT, pQKV, pBq, nullptr,
        256, 0, 1024LL*512, 768LL*1024, 512, 512, 1024);
    split_v<<<(int)((16LL*256*1024 + 255)/256), 256>>>(pQKV, pV2);

    // 3) Qp^T / Kp^T (split, n-major)
    prep_qkT<<<dim3(32, 4, B_*HEADS), dim3(32, 32)>>>(pQKV, rel_h, rel_w, pQpT, pKpT);

    // 4-6) fused attention: S, softmax, P.V in one kernel
    flash_attn<<<dim3(8, 64), 256, SMFA>>>(pQpT, pKpT, pV2, pOt);

    // 7) LayerNorm -> y^T split
    ln_yT<<<dim3(32, B_), 256>>>(pOt, ln_w, ln_b, pYT);

    // 8) expand + exact GELU + residual (M=1024, N=1024, Kseg=256)
    mma3<128,1><<<dim3(8, 8, B_), 256, SM128>>>(pW1, pYT, out, nullptr, x,
        256, 0, 1024LL*512, 1024LL*1024, 512, 512, 1024);
}